// round 7
// baseline (speedup 1.0000x reference)
#include <cuda_runtime.h>
#include <cuda_fp16.h>
#include <cstdint>

#define NPAT 50000
#define NCON 20000
#define NN   70000
#define EE   800000
#define HH   128
#define LL   2

// ---------------- scratch (static device globals; no allocs allowed) ----------------
__device__ float g_buf0[(size_t)NN * HH];
__device__ float g_buf1[(size_t)NN * HH];
__device__ float g_agg [(size_t)NN * HH];
__device__ int   g_deg [NN];
__device__ float g_rcnt[NN];
__device__ int   g_off [NN + 1];
__device__ int   g_cur [NN];
__device__ int   g_csr [2 * EE];
// pre-transposed/split weights: [variant(4)*split(2)][k(256)][n(128)]
__device__ float g_B[(size_t)8 * 256 * 128];

// ---------------- helpers ----------------
__device__ __forceinline__ float cvt_tf32(float v) {
    float h; asm("cvt.rna.tf32.f32 %0, %1;" : "=f"(h) : "f"(v)); return h;
}
__device__ __forceinline__ uint32_t smem_u32(const void* p) {
    uint32_t a;
    asm("{ .reg .u64 t; cvta.to.shared.u64 t, %1; cvt.u32.u64 %0, t; }" : "=r"(a) : "l"(p));
    return a;
}
__device__ __forceinline__ void cp_async16(uint32_t saddr, const void* gptr) {
    asm volatile("cp.async.ca.shared.global [%0], [%1], 16;" :: "r"(saddr), "l"(gptr));
}
__device__ __forceinline__ void cp_commit() {
    asm volatile("cp.async.commit_group;");
}
template <int N>
__device__ __forceinline__ void cp_wait() {
    asm volatile("cp.async.wait_group %0;" :: "n"(N));
}

__device__ __forceinline__ void mma_tf32(float* c, const uint32_t* a, const uint32_t* b) {
    asm volatile(
        "mma.sync.aligned.m16n8k8.row.col.f32.tf32.tf32.f32 "
        "{%0,%1,%2,%3}, {%4,%5,%6,%7}, {%8,%9}, {%0,%1,%2,%3};"
        : "+f"(c[0]), "+f"(c[1]), "+f"(c[2]), "+f"(c[3])
        : "r"(a[0]), "r"(a[1]), "r"(a[2]), "r"(a[3]),
          "r"(b[0]), "r"(b[1]));
}

// ---------------- degree histogram ----------------
__global__ void deg_kernel(const int* __restrict__ dst_pc, const int* __restrict__ dst_cp,
                           int* __restrict__ deg) {
    int i = blockIdx.x * blockDim.x + threadIdx.x;
    if (i < EE)               atomicAdd(&deg[NPAT + dst_pc[i]], 1);
    else if (i < 2 * EE)      atomicAdd(&deg[dst_cp[i - EE]], 1);
}

// ---------------- single-block exclusive scan (+ rcnt + cur zero) -------------------
__global__ void scan_kernel(const int* __restrict__ deg, int* __restrict__ off,
                            float* __restrict__ rcnt, int* __restrict__ cur) {
    __shared__ int ssum[1024];
    int tid = threadIdx.x;
    const int PER = (NN + 1023) / 1024;
    int base = tid * PER;
    int s = 0;
    for (int i = 0; i < PER; i++) { int idx = base + i; if (idx < NN) s += deg[idx]; }
    ssum[tid] = s;
    __syncthreads();
    for (int ofs = 1; ofs < 1024; ofs <<= 1) {
        int v = (tid >= ofs) ? ssum[tid - ofs] : 0;
        __syncthreads();
        ssum[tid] += v;
        __syncthreads();
    }
    int run = (tid == 0) ? 0 : ssum[tid - 1];
    for (int i = 0; i < PER; i++) {
        int idx = base + i;
        if (idx < NN) {
            int d = deg[idx];
            off[idx] = run; run += d;
            rcnt[idx] = 1.0f / (float)max(d, 1);
            cur[idx] = 0;
        }
    }
    if (tid == 0) off[NN] = ssum[1023];
}

// ---------------- CSR fill ----------------
__global__ void fill_kernel(const int* __restrict__ src_pc, const int* __restrict__ dst_pc,
                            const int* __restrict__ src_cp, const int* __restrict__ dst_cp,
                            const int* __restrict__ off, int* __restrict__ cur,
                            int* __restrict__ csr) {
    int i = blockIdx.x * blockDim.x + threadIdx.x;
    int s, d;
    if (i < EE)          { s = src_pc[i];             d = NPAT + dst_pc[i]; }
    else if (i < 2 * EE) { s = NPAT + src_cp[i - EE]; d = dst_cp[i - EE]; }
    else return;
    int pos = off[d] + atomicAdd(&cur[d], 1);
    csr[pos] = s;
}

// ---------------- fp32 gather-aggregate (round-4, measured good) --------------------
__global__ void gather_kernel(const float* __restrict__ X,
                              const int* __restrict__ off, const int* __restrict__ csr,
                              const float* __restrict__ rcnt, float* __restrict__ AGG) {
    int warp = (int)((blockIdx.x * (long long)blockDim.x + threadIdx.x) >> 5);
    if (warp >= NN) return;
    int lane = threadIdx.x & 31;
    int beg = off[warp], end = off[warp + 1];
    float4 acc = make_float4(0.f, 0.f, 0.f, 0.f);
    int e = beg;
    for (; e + 32 <= end; e += 32) {
        int idx = csr[e + lane];
#pragma unroll
        for (int j = 0; j < 32; j++) {
            int s = __shfl_sync(0xffffffffu, idx, j);
            float4 v = ((const float4*)(X + (size_t)s * HH))[lane];
            acc.x += v.x; acc.y += v.y; acc.z += v.z; acc.w += v.w;
        }
    }
    int rem = end - e;
    if (rem > 0) {
        int idx = (lane < rem) ? csr[e + lane] : 0;
        for (int j = 0; j < rem; j++) {
            int s = __shfl_sync(0xffffffffu, idx, j);
            float4 v = ((const float4*)(X + (size_t)s * HH))[lane];
            acc.x += v.x; acc.y += v.y; acc.z += v.z; acc.w += v.w;
        }
    }
    float rc = rcnt[warp];
    ((float4*)(AGG + (size_t)warp * HH))[lane] =
        make_float4(acc.x * rc, acc.y * rc, acc.z * rc, acc.w * rc);
}

// ---------------- input projection (FFMA, round-4) ----------------------------------
template <int K>
__global__ void proj_kernel(const float* __restrict__ A, const float* __restrict__ W,
                            const float* __restrict__ bias, float* __restrict__ C, int M) {
    extern __shared__ float sm[];
    float* sW = sm;
    float* sA = sm + K * 128;
    int tid = threadIdx.x;

    float4* sW4 = (float4*)sW;
    const float4* Wg = (const float4*)W;
    for (int i = tid; i < K * 32; i += 256) sW4[i] = Wg[i];
    {
        int row = tid >> 2, q = tid & 3;
        int r = blockIdx.x * 64 + row;
        const int f4p = K / 16;
        float4* dst = (float4*)(sA + row * K) + q * f4p;
        if (r < M) {
            const float4* Ar = (const float4*)(A + (size_t)r * K) + q * f4p;
#pragma unroll
            for (int i = 0; i < f4p; i++) dst[i] = Ar[i];
        } else {
#pragma unroll
            for (int i = 0; i < f4p; i++) dst[i] = make_float4(0.f, 0.f, 0.f, 0.f);
        }
    }
    __syncthreads();

    int rg = tid >> 5, cg = tid & 31;
    float4 acc[8];
#pragma unroll
    for (int i = 0; i < 8; i++) acc[i] = make_float4(0.f, 0.f, 0.f, 0.f);
    const float4* sA4 = (const float4*)sA;
#pragma unroll 2
    for (int k4 = 0; k4 < K / 4; k4++) {
        float4 w0 = sW4[(4 * k4 + 0) * 32 + cg];
        float4 w1 = sW4[(4 * k4 + 1) * 32 + cg];
        float4 w2 = sW4[(4 * k4 + 2) * 32 + cg];
        float4 w3 = sW4[(4 * k4 + 3) * 32 + cg];
#pragma unroll
        for (int i = 0; i < 8; i++) {
            float4 a = sA4[(rg * 8 + i) * (K / 4) + k4];
            acc[i].x += a.x * w0.x + a.y * w1.x + a.z * w2.x + a.w * w3.x;
            acc[i].y += a.x * w0.y + a.y * w1.y + a.z * w2.y + a.w * w3.y;
            acc[i].z += a.x * w0.z + a.y * w1.z + a.z * w2.z + a.w * w3.z;
            acc[i].w += a.x * w0.w + a.y * w1.w + a.z * w2.w + a.w * w3.w;
        }
    }
    float4 bb = ((const float4*)bias)[cg];
#pragma unroll
    for (int i = 0; i < 8; i++) {
        int r = blockIdx.x * 64 + rg * 8 + i;
        if (r < M) {
            float4 v = make_float4(acc[i].x + bb.x, acc[i].y + bb.y,
                                   acc[i].z + bb.z, acc[i].w + bb.w);
            ((float4*)(C + (size_t)r * HH))[cg] = v;
        }
    }
}

// ---------------- weight prep: transpose + tf32-split (round-4 layout) --------------
__global__ void prepB_kernel(const float* __restrict__ W_root, const float* __restrict__ W_rel,
                             float* __restrict__ B) {
    int i = blockIdx.x * blockDim.x + threadIdx.x;
    if (i >= 4 * 256 * 128) return;
    int n = i & 127;
    int k = (i >> 7) & 255;
    int v = i >> 15;
    int l = v >> 1, type = v & 1;
    float val;
    if (k < 128) {
        val = W_root[((size_t)l * 128 + k) * 128 + n];
    } else {
        int rel = (type == 0) ? 1 : 0;
        val = W_rel[(((size_t)l * 2 + rel) * 128 + (k - 128)) * 128 + n];
    }
    float hi = cvt_tf32(val);
    float lo = val - hi;
    B[(((size_t)(v * 2 + 0)) * 256 + k) * 128 + n] = hi;
    B[(((size_t)(v * 2 + 1)) * 256 + k) * 128 + n] = lo;
}

// ---------------- mma.sync tf32 layer: round-4 + cp.async double-buffered B ---------
#define ASTR 36
#define BSTR 136
#define SM_AHI 0
#define SM_ALO (128 * ASTR)
#define SM_B   (2 * 128 * ASTR)            // start of B buffers
#define B_BUF  (2 * 32 * BSTR)             // floats per B buffer (hi+lo)
#define B_LO   (32 * BSTR)                 // lo offset within a buffer
#define SM_FLOATS (SM_B + 2 * B_BUF)       // 9216 + 17408 = 26624 floats (106.5 KB)

__global__ void __launch_bounds__(256, 2)
layer_mma_kernel(const float* __restrict__ X, const float* __restrict__ AGG,
                 const float* __restrict__ Bglob, const float* __restrict__ bias,
                 float* __restrict__ C, int layer) {
    extern __shared__ float sm[];
    uint32_t smem_base = smem_u32(sm);
    int tid = threadIdx.x, wid = tid >> 5, lane = tid & 31;
    int warpM = wid & 3, warpN = wid >> 2;

    const int NBP_T = (NPAT + 127) / 128;   // 391
    int bid = blockIdx.x;
    int base, rowlim, v;
    if (bid < NBP_T) { base = bid * 128;                  rowlim = NPAT; v = layer * 2; }
    else             { base = NPAT + (bid - NBP_T) * 128; rowlim = NN;   v = layer * 2 + 1; }

    // per-thread cp.async targets (same smem mapping as round-4's B copy)
    uint32_t boff[4];
    const float4* bhsrc = (const float4*)(Bglob + ((size_t)(v * 2 + 0)) * 256 * 128);
    const float4* blsrc = (const float4*)(Bglob + ((size_t)(v * 2 + 1)) * 256 * 128);
#pragma unroll
    for (int i = 0; i < 4; i++) {
        int idx = tid + 256 * i;
        int kk = idx >> 5, n4 = idx & 31;
        boff[i] = (uint32_t)((kk * BSTR + n4 * 4) * 4);
    }

    float acc[2][8][4];
#pragma unroll
    for (int mt = 0; mt < 2; mt++)
#pragma unroll
        for (int nt = 0; nt < 8; nt++)
#pragma unroll
            for (int r = 0; r < 4; r++) acc[mt][nt][r] = 0.f;

    int arow = tid >> 1;
    int node = base + arow;
    bool valid = node < rowlim;
    int f4base = (tid & 1) * 4;

    // prologue: prefetch B chunk 0 into buffer 0
    {
        uint32_t bb = smem_base + (uint32_t)(SM_B * 4);
#pragma unroll
        for (int i = 0; i < 4; i++) {
            int idx = tid + 256 * i;
            cp_async16(bb + boff[i],                 bhsrc + idx);
            cp_async16(bb + (uint32_t)(B_LO * 4) + boff[i], blsrc + idx);
        }
        cp_commit();
    }

    for (int chunk = 0; chunk < 8; chunk++) {
        // ---- A chunk: load, split hi/lo (overlaps in-flight B prefetch) ----
        const float* src = (chunk < 4)
            ? (X   + (size_t)node * HH + chunk * 32)
            : (AGG + (size_t)node * HH + (chunk - 4) * 32);
#pragma unroll
        for (int i = 0; i < 4; i++) {
            int f4 = f4base + i;
            float4 a = valid ? ((const float4*)src)[f4] : make_float4(0.f, 0.f, 0.f, 0.f);
            float4 hi4, lo4;
            hi4.x = cvt_tf32(a.x); lo4.x = a.x - hi4.x;
            hi4.y = cvt_tf32(a.y); lo4.y = a.y - hi4.y;
            hi4.z = cvt_tf32(a.z); lo4.z = a.z - hi4.z;
            hi4.w = cvt_tf32(a.w); lo4.w = a.w - hi4.w;
            *(float4*)&sm[SM_AHI + arow * ASTR + f4 * 4] = hi4;
            *(float4*)&sm[SM_ALO + arow * ASTR + f4 * 4] = lo4;
        }
        // ---- prefetch next B chunk into alternate buffer ----
        if (chunk < 7) {
            uint32_t bb = smem_base + (uint32_t)((SM_B + ((chunk + 1) & 1) * B_BUF) * 4);
            int gofs = (chunk + 1) * 32 * 32;   // float4 offset of chunk in [256][128]
#pragma unroll
            for (int i = 0; i < 4; i++) {
                int idx = tid + 256 * i;
                cp_async16(bb + boff[i],                 bhsrc + gofs + idx);
                cp_async16(bb + (uint32_t)(B_LO * 4) + boff[i], blsrc + gofs + idx);
            }
            cp_commit();
            cp_wait<1>();    // current chunk's B has landed; next stays in flight
        } else {
            cp_wait<0>();
        }
        __syncthreads();

        const int BHI = SM_B + (chunk & 1) * B_BUF;
        const int BLO = BHI + B_LO;
#pragma unroll
        for (int k8 = 0; k8 < 4; k8++) {
            int k0 = k8 * 8;
            uint32_t ah[2][4], al[2][4];
#pragma unroll
            for (int mt = 0; mt < 2; mt++) {
                int r0 = warpM * 32 + mt * 16 + (lane >> 2);
                int c0 = k0 + (lane & 3);
                ah[mt][0] = __float_as_uint(sm[SM_AHI + r0 * ASTR + c0]);
                ah[mt][1] = __float_as_uint(sm[SM_AHI + (r0 + 8) * ASTR + c0]);
                ah[mt][2] = __float_as_uint(sm[SM_AHI + r0 * ASTR + c0 + 4]);
                ah[mt][3] = __float_as_uint(sm[SM_AHI + (r0 + 8) * ASTR + c0 + 4]);
                al[mt][0] = __float_as_uint(sm[SM_ALO + r0 * ASTR + c0]);
                al[mt][1] = __float_as_uint(sm[SM_ALO + (r0 + 8) * ASTR + c0]);
                al[mt][2] = __float_as_uint(sm[SM_ALO + r0 * ASTR + c0 + 4]);
                al[mt][3] = __float_as_uint(sm[SM_ALO + (r0 + 8) * ASTR + c0 + 4]);
            }
#pragma unroll
            for (int nt = 0; nt < 8; nt++) {
                int n = warpN * 64 + nt * 8 + (lane >> 2);
                int kr = k0 + (lane & 3);
                uint32_t bh[2], bl[2];
                bh[0] = __float_as_uint(sm[BHI + kr * BSTR + n]);
                bh[1] = __float_as_uint(sm[BHI + (kr + 4) * BSTR + n]);
                bl[0] = __float_as_uint(sm[BLO + kr * BSTR + n]);
                bl[1] = __float_as_uint(sm[BLO + (kr + 4) * BSTR + n]);
#pragma unroll
                for (int mt = 0; mt < 2; mt++) {
                    mma_tf32(acc[mt][nt], ah[mt], bh);
                    mma_tf32(acc[mt][nt], ah[mt], bl);
                    mma_tf32(acc[mt][nt], al[mt], bh);
                }
            }
        }
        __syncthreads();
    }

#pragma unroll
    for (int mt = 0; mt < 2; mt++) {
        int row = base + warpM * 32 + mt * 16 + (lane >> 2);
#pragma unroll
        for (int nt = 0; nt < 8; nt++) {
            int col = warpN * 64 + nt * 8 + (lane & 3) * 2;
            float2 bv = *(const float2*)&bias[col];
            if (row < rowlim) {
                float2 o;
                o.x = fmaxf(acc[mt][nt][0] + bv.x, 0.f);
                o.y = fmaxf(acc[mt][nt][1] + bv.y, 0.f);
                *(float2*)&C[(size_t)row * HH + col] = o;
            }
            if (row + 8 < rowlim) {
                float2 o;
                o.x = fmaxf(acc[mt][nt][2] + bv.x, 0.f);
                o.y = fmaxf(acc[mt][nt][3] + bv.y, 0.f);
                *(float2*)&C[(size_t)(row + 8) * HH + col] = o;
            }
        }
    }
}

// ---------------- launch ----------------
extern "C" void kernel_launch(void* const* d_in, const int* in_sizes, int n_in,
                              void* d_out, int out_size) {
    const float* x_patient = (const float*)d_in[0];
    const float* x_concept = (const float*)d_in[1];
    const float* W_p    = (const float*)d_in[2];
    const float* b_p    = (const float*)d_in[3];
    const float* W_c    = (const float*)d_in[4];
    const float* b_c    = (const float*)d_in[5];
    const float* W_root = (const float*)d_in[6];
    const float* b_root = (const float*)d_in[7];
    const float* W_rel  = (const float*)d_in[8];
    const int* src_pc = (const int*)d_in[9];
    const int* dst_pc = (const int*)d_in[10];
    const int* src_cp = (const int*)d_in[11];
    const int* dst_cp = (const int*)d_in[12];
    float* out = (float*)d_out;

    float *buf0, *buf1, *agg, *rcnt, *Bg;
    int *deg, *off, *cur, *csr;
    cudaGetSymbolAddress((void**)&buf0, g_buf0);
    cudaGetSymbolAddress((void**)&buf1, g_buf1);
    cudaGetSymbolAddress((void**)&agg,  g_agg);
    cudaGetSymbolAddress((void**)&rcnt, g_rcnt);
    cudaGetSymbolAddress((void**)&deg,  g_deg);
    cudaGetSymbolAddress((void**)&off,  g_off);
    cudaGetSymbolAddress((void**)&cur,  g_cur);
    cudaGetSymbolAddress((void**)&csr,  g_csr);
    cudaGetSymbolAddress((void**)&Bg,   g_B);

    const int PROJ64_SMEM  = (64  * 128 + 64 * 64 ) * 4;
    const int PROJ128_SMEM = (128 * 128 + 64 * 128) * 4;
    const int LAYER_SMEM   = SM_FLOATS * 4;              // 106496 B
    cudaFuncSetAttribute(proj_kernel<64>,  cudaFuncAttributeMaxDynamicSharedMemorySize, PROJ64_SMEM);
    cudaFuncSetAttribute(proj_kernel<128>, cudaFuncAttributeMaxDynamicSharedMemorySize, PROJ128_SMEM);
    cudaFuncSetAttribute(layer_mma_kernel, cudaFuncAttributeMaxDynamicSharedMemorySize, LAYER_SMEM);

    // ---- CSR build ----
    cudaMemsetAsync(deg, 0, NN * sizeof(int));
    deg_kernel<<<(2 * EE + 255) / 256, 256>>>(dst_pc, dst_cp, deg);
    scan_kernel<<<1, 1024>>>(deg, off, rcnt, cur);
    fill_kernel<<<(2 * EE + 255) / 256, 256>>>(src_pc, dst_pc, src_cp, dst_cp, off, cur, csr);

    // ---- weight prep ----
    prepB_kernel<<<(4 * 256 * 128 + 255) / 256, 256>>>(W_root, W_rel, Bg);

    // ---- projections (FFMA, round-4) ----
    proj_kernel<64><<<(NPAT + 63) / 64, 256, PROJ64_SMEM>>>(x_patient, W_p, b_p, buf0, NPAT);
    proj_kernel<128><<<(NCON + 63) / 64, 256, PROJ128_SMEM>>>(x_concept, W_c, b_c,
                                                              buf0 + (size_t)NPAT * HH, NCON);

    const int NB_TC = (NPAT + 127) / 128 + (NCON + 127) / 128;  // 548
    const int GATHER_BLOCKS = (NN + 7) / 8;

    for (int l = 0; l < LL; l++) {
        const float* in  = (l == 0) ? buf0 : buf1;
        float*       dst = (l == 0) ? buf1 : out;
        gather_kernel<<<GATHER_BLOCKS, 256>>>(in, off, csr, rcnt, agg);
        layer_mma_kernel<<<NB_TC, 256, LAYER_SMEM>>>(in, agg, Bg,
                                                     b_root + (size_t)l * HH, dst, l);
    }
}

// round 8
// speedup vs baseline: 1.1729x; 1.1729x over previous
#include <cuda_runtime.h>
#include <cuda_bf16.h>
#include <cstdint>

#define NPAT 50000
#define NCON 20000
#define NN   70000
#define EE   800000
#define HH   128
#define LL   2

// ---------------- scratch (static device globals; no allocs allowed) ----------------
__device__ float g_buf0[(size_t)NN * HH];
__device__ float g_buf1[(size_t)NN * HH];
__device__ float g_agg [(size_t)NN * HH];
__device__ int   g_deg [NN];
__device__ float g_rcnt[NN];
__device__ int   g_off [NN + 1];
__device__ int   g_cur [NN];
__device__ int   g_csr [2 * EE];
// pre-transposed/split weights: [variant(4)*split(2)][k(256)][n(128)]
__device__ float g_B[(size_t)8 * 256 * 128];

// ---------------- helpers ----------------
__device__ __forceinline__ float cvt_tf32(float v) {
    float h; asm("cvt.rna.tf32.f32 %0, %1;" : "=f"(h) : "f"(v)); return h;
}

__device__ __forceinline__ void mma_tf32(float* c, const uint32_t* a, const uint32_t* b) {
    asm volatile(
        "mma.sync.aligned.m16n8k8.row.col.f32.tf32.tf32.f32 "
        "{%0,%1,%2,%3}, {%4,%5,%6,%7}, {%8,%9}, {%0,%1,%2,%3};"
        : "+f"(c[0]), "+f"(c[1]), "+f"(c[2]), "+f"(c[3])
        : "r"(a[0]), "r"(a[1]), "r"(a[2]), "r"(a[3]),
          "r"(b[0]), "r"(b[1]));
}

// ---------------- degree histogram ----------------
__global__ void deg_kernel(const int* __restrict__ dst_pc, const int* __restrict__ dst_cp,
                           int* __restrict__ deg) {
    int i = blockIdx.x * blockDim.x + threadIdx.x;
    if (i < EE)               atomicAdd(&deg[NPAT + dst_pc[i]], 1);
    else if (i < 2 * EE)      atomicAdd(&deg[dst_cp[i - EE]], 1);
}

__global__ void rcnt_kernel(const int* __restrict__ deg, float* __restrict__ rcnt) {
    int i = blockIdx.x * blockDim.x + threadIdx.x;
    if (i < NN) rcnt[i] = 1.0f / (float)max(deg[i], 1);
}

// ---------------- single-block exclusive scan ----------------
__global__ void scan_kernel(const int* __restrict__ deg, int* __restrict__ off) {
    __shared__ int ssum[1024];
    int tid = threadIdx.x;
    const int PER = (NN + 1023) / 1024;
    int base = tid * PER;
    int s = 0;
    for (int i = 0; i < PER; i++) { int idx = base + i; if (idx < NN) s += deg[idx]; }
    ssum[tid] = s;
    __syncthreads();
    for (int ofs = 1; ofs < 1024; ofs <<= 1) {
        int v = (tid >= ofs) ? ssum[tid - ofs] : 0;
        __syncthreads();
        ssum[tid] += v;
        __syncthreads();
    }
    int run = (tid == 0) ? 0 : ssum[tid - 1];
    for (int i = 0; i < PER; i++) {
        int idx = base + i;
        if (idx < NN) { off[idx] = run; run += deg[idx]; }
    }
    if (tid == 0) off[NN] = ssum[1023];
}

// ---------------- CSR fill ----------------
__global__ void fill_kernel(const int* __restrict__ src_pc, const int* __restrict__ dst_pc,
                            const int* __restrict__ src_cp, const int* __restrict__ dst_cp,
                            const int* __restrict__ off, int* __restrict__ cur,
                            int* __restrict__ csr) {
    int i = blockIdx.x * blockDim.x + threadIdx.x;
    int s, d;
    if (i < EE)          { s = src_pc[i];             d = NPAT + dst_pc[i]; }
    else if (i < 2 * EE) { s = NPAT + src_cp[i - EE]; d = dst_cp[i - EE]; }
    else return;
    int pos = off[d] + atomicAdd(&cur[d], 1);
    csr[pos] = s;
}

// ---------------- gather-aggregate ----------------
__global__ void gather_kernel(const float* __restrict__ X,
                              const int* __restrict__ off, const int* __restrict__ csr,
                              const float* __restrict__ rcnt, float* __restrict__ AGG) {
    int warp = (int)((blockIdx.x * (long long)blockDim.x + threadIdx.x) >> 5);
    if (warp >= NN) return;
    int lane = threadIdx.x & 31;
    int beg = off[warp], end = off[warp + 1];
    float4 acc = make_float4(0.f, 0.f, 0.f, 0.f);
    int e = beg;
    for (; e + 32 <= end; e += 32) {
        int idx = csr[e + lane];
#pragma unroll
        for (int j = 0; j < 32; j++) {
            int s = __shfl_sync(0xffffffffu, idx, j);
            float4 v = ((const float4*)(X + (size_t)s * HH))[lane];
            acc.x += v.x; acc.y += v.y; acc.z += v.z; acc.w += v.w;
        }
    }
    int rem = end - e;
    if (rem > 0) {
        int idx = (lane < rem) ? csr[e + lane] : 0;
        for (int j = 0; j < rem; j++) {
            int s = __shfl_sync(0xffffffffu, idx, j);
            float4 v = ((const float4*)(X + (size_t)s * HH))[lane];
            acc.x += v.x; acc.y += v.y; acc.z += v.z; acc.w += v.w;
        }
    }
    float rc = rcnt[warp];
    ((float4*)(AGG + (size_t)warp * HH))[lane] =
        make_float4(acc.x * rc, acc.y * rc, acc.z * rc, acc.w * rc);
}

// ---------------- input projection (FFMA): C[M,128] = A[M,K] @ W[K,128] + b ---------
template <int K>
__global__ void proj_kernel(const float* __restrict__ A, const float* __restrict__ W,
                            const float* __restrict__ bias, float* __restrict__ C, int M) {
    extern __shared__ float sm[];
    float* sW = sm;
    float* sA = sm + K * 128;
    int tid = threadIdx.x;

    float4* sW4 = (float4*)sW;
    const float4* Wg = (const float4*)W;
    for (int i = tid; i < K * 32; i += 256) sW4[i] = Wg[i];
    {
        int row = tid >> 2, q = tid & 3;
        int r = blockIdx.x * 64 + row;
        const int f4p = K / 16;
        float4* dst = (float4*)(sA + row * K) + q * f4p;
        if (r < M) {
            const float4* Ar = (const float4*)(A + (size_t)r * K) + q * f4p;
#pragma unroll
            for (int i = 0; i < f4p; i++) dst[i] = Ar[i];
        } else {
#pragma unroll
            for (int i = 0; i < f4p; i++) dst[i] = make_float4(0.f, 0.f, 0.f, 0.f);
        }
    }
    __syncthreads();

    int rg = tid >> 5, cg = tid & 31;
    float4 acc[8];
#pragma unroll
    for (int i = 0; i < 8; i++) acc[i] = make_float4(0.f, 0.f, 0.f, 0.f);
    const float4* sA4 = (const float4*)sA;
#pragma unroll 2
    for (int k4 = 0; k4 < K / 4; k4++) {
        float4 w0 = sW4[(4 * k4 + 0) * 32 + cg];
        float4 w1 = sW4[(4 * k4 + 1) * 32 + cg];
        float4 w2 = sW4[(4 * k4 + 2) * 32 + cg];
        float4 w3 = sW4[(4 * k4 + 3) * 32 + cg];
#pragma unroll
        for (int i = 0; i < 8; i++) {
            float4 a = sA4[(rg * 8 + i) * (K / 4) + k4];
            acc[i].x += a.x * w0.x + a.y * w1.x + a.z * w2.x + a.w * w3.x;
            acc[i].y += a.x * w0.y + a.y * w1.y + a.z * w2.y + a.w * w3.y;
            acc[i].z += a.x * w0.z + a.y * w1.z + a.z * w2.z + a.w * w3.z;
            acc[i].w += a.x * w0.w + a.y * w1.w + a.z * w2.w + a.w * w3.w;
        }
    }
    float4 bb = ((const float4*)bias)[cg];
#pragma unroll
    for (int i = 0; i < 8; i++) {
        int r = blockIdx.x * 64 + rg * 8 + i;
        if (r < M) {
            float4 v = make_float4(acc[i].x + bb.x, acc[i].y + bb.y,
                                   acc[i].z + bb.z, acc[i].w + bb.w);
            ((float4*)(C + (size_t)r * HH))[cg] = v;
        }
    }
}

// ---------------- weight prep: transpose + tf32-split ------------------------------
// variant v: l = v>>1, type = v&1 (0 = patient rows -> [Wroot;Wrel[1]]; 1 = concept -> Wrel[0])
__global__ void prepB_kernel(const float* __restrict__ W_root, const float* __restrict__ W_rel,
                             float* __restrict__ B) {
    int i = blockIdx.x * blockDim.x + threadIdx.x;
    if (i >= 4 * 256 * 128) return;
    int n = i & 127;
    int k = (i >> 7) & 255;
    int v = i >> 15;
    int l = v >> 1, type = v & 1;
    float val;
    if (k < 128) {
        val = W_root[((size_t)l * 128 + k) * 128 + n];
    } else {
        int rel = (type == 0) ? 1 : 0;
        val = W_rel[(((size_t)l * 2 + rel) * 128 + (k - 128)) * 128 + n];
    }
    float hi = cvt_tf32(val);
    float lo = val - hi;
    B[(((size_t)(v * 2 + 0)) * 256 + k) * 128 + n] = hi;
    B[(((size_t)(v * 2 + 1)) * 256 + k) * 128 + n] = lo;
}

// ---------------- mma.sync tf32 layer: out = relu([x|agg] @ Bv + b) ------------------
// CTA: M=128, N=128, K=256 in 8 chunks of 32. 8 warps: warpM = wid&3, warpN = wid>>2.
// smem strides: A 36 floats/row (pad 4), B 136 floats/row (pad 8) -> conflict-free frags.
#define ASTR 36
#define BSTR 136
#define SM_AHI 0
#define SM_ALO (128 * ASTR)
#define SM_BHI (2 * 128 * ASTR)
#define SM_BLO (2 * 128 * ASTR + 32 * BSTR)
#define SM_FLOATS (2 * 128 * ASTR + 2 * 32 * BSTR)

__global__ void __launch_bounds__(256, 2)
layer_mma_kernel(const float* __restrict__ X, const float* __restrict__ AGG,
                 const float* __restrict__ Bglob, const float* __restrict__ bias,
                 float* __restrict__ C, int layer) {
    extern __shared__ float sm[];
    int tid = threadIdx.x, wid = tid >> 5, lane = tid & 31;
    int warpM = wid & 3, warpN = wid >> 2;

    const int NBP_T = (NPAT + 127) / 128;   // 391
    int bid = blockIdx.x;
    int base, rowlim, v;
    if (bid < NBP_T) { base = bid * 128;                  rowlim = NPAT; v = layer * 2; }
    else             { base = NPAT + (bid - NBP_T) * 128; rowlim = NN;   v = layer * 2 + 1; }

    float acc[2][8][4];
#pragma unroll
    for (int mt = 0; mt < 2; mt++)
#pragma unroll
        for (int nt = 0; nt < 8; nt++)
#pragma unroll
            for (int r = 0; r < 4; r++) acc[mt][nt][r] = 0.f;

    int arow = tid >> 1;
    int node = base + arow;
    bool valid = node < rowlim;
    int f4base = (tid & 1) * 4;

    for (int chunk = 0; chunk < 8; chunk++) {
        const float* src = (chunk < 4)
            ? (X   + (size_t)node * HH + chunk * 32)
            : (AGG + (size_t)node * HH + (chunk - 4) * 32);
#pragma unroll
        for (int i = 0; i < 4; i++) {
            int f4 = f4base + i;
            float4 a = valid ? ((const float4*)src)[f4] : make_float4(0.f, 0.f, 0.f, 0.f);
            float4 hi4, lo4;
            hi4.x = cvt_tf32(a.x); lo4.x = a.x - hi4.x;
            hi4.y = cvt_tf32(a.y); lo4.y = a.y - hi4.y;
            hi4.z = cvt_tf32(a.z); lo4.z = a.z - hi4.z;
            hi4.w = cvt_tf32(a.w); lo4.w = a.w - hi4.w;
            *(float4*)&sm[SM_AHI + arow * ASTR + f4 * 4] = hi4;
            *(float4*)&sm[SM_ALO + arow * ASTR + f4 * 4] = lo4;
        }
        {
            const float4* bh = (const float4*)(Bglob + (((size_t)(v * 2 + 0)) * 256 + chunk * 32) * 128);
            const float4* bl = (const float4*)(Bglob + (((size_t)(v * 2 + 1)) * 256 + chunk * 32) * 128);
#pragma unroll
            for (int i = 0; i < 4; i++) {
                int idx = tid + 256 * i;          // < 1024
                int kk = idx >> 5, n4 = idx & 31;
                *(float4*)&sm[SM_BHI + kk * BSTR + n4 * 4] = bh[idx];
                *(float4*)&sm[SM_BLO + kk * BSTR + n4 * 4] = bl[idx];
            }
        }
        __syncthreads();

#pragma unroll
        for (int k8 = 0; k8 < 4; k8++) {
            int k0 = k8 * 8;
            uint32_t ah[2][4], al[2][4];
#pragma unroll
            for (int mt = 0; mt < 2; mt++) {
                int r0 = warpM * 32 + mt * 16 + (lane >> 2);
                int c0 = k0 + (lane & 3);
                ah[mt][0] = __float_as_uint(sm[SM_AHI + r0 * ASTR + c0]);
                ah[mt][1] = __float_as_uint(sm[SM_AHI + (r0 + 8) * ASTR + c0]);
                ah[mt][2] = __float_as_uint(sm[SM_AHI + r0 * ASTR + c0 + 4]);
                ah[mt][3] = __float_as_uint(sm[SM_AHI + (r0 + 8) * ASTR + c0 + 4]);
                al[mt][0] = __float_as_uint(sm[SM_ALO + r0 * ASTR + c0]);
                al[mt][1] = __float_as_uint(sm[SM_ALO + (r0 + 8) * ASTR + c0]);
                al[mt][2] = __float_as_uint(sm[SM_ALO + r0 * ASTR + c0 + 4]);
                al[mt][3] = __float_as_uint(sm[SM_ALO + (r0 + 8) * ASTR + c0 + 4]);
            }
#pragma unroll
            for (int nt = 0; nt < 8; nt++) {
                int n = warpN * 64 + nt * 8 + (lane >> 2);
                int kr = k0 + (lane & 3);
                uint32_t bh[2], bl[2];
                bh[0] = __float_as_uint(sm[SM_BHI + kr * BSTR + n]);
                bh[1] = __float_as_uint(sm[SM_BHI + (kr + 4) * BSTR + n]);
                bl[0] = __float_as_uint(sm[SM_BLO + kr * BSTR + n]);
                bl[1] = __float_as_uint(sm[SM_BLO + (kr + 4) * BSTR + n]);
#pragma unroll
                for (int mt = 0; mt < 2; mt++) {
                    mma_tf32(acc[mt][nt], ah[mt], bh);
                    mma_tf32(acc[mt][nt], ah[mt], bl);
                    mma_tf32(acc[mt][nt], al[mt], bh);
                }
            }
        }
        __syncthreads();
    }

    // ---- epilogue: bias + relu, direct global stores ----
#pragma unroll
    for (int mt = 0; mt < 2; mt++) {
        int row = base + warpM * 32 + mt * 16 + (lane >> 2);
#pragma unroll
        for (int nt = 0; nt < 8; nt++) {
            int col = warpN * 64 + nt * 8 + (lane & 3) * 2;
            float2 bv = *(const float2*)&bias[col];
            if (row < rowlim) {
                float2 o;
                o.x = fmaxf(acc[mt][nt][0] + bv.x, 0.f);
                o.y = fmaxf(acc[mt][nt][1] + bv.y, 0.f);
                *(float2*)&C[(size_t)row * HH + col] = o;
            }
            if (row + 8 < rowlim) {
                float2 o;
                o.x = fmaxf(acc[mt][nt][2] + bv.x, 0.f);
                o.y = fmaxf(acc[mt][nt][3] + bv.y, 0.f);
                *(float2*)&C[(size_t)(row + 8) * HH + col] = o;
            }
        }
    }
}

// ---------------- launch ----------------
extern "C" void kernel_launch(void* const* d_in, const int* in_sizes, int n_in,
                              void* d_out, int out_size) {
    const float* x_patient = (const float*)d_in[0];
    const float* x_concept = (const float*)d_in[1];
    const float* W_p    = (const float*)d_in[2];
    const float* b_p    = (const float*)d_in[3];
    const float* W_c    = (const float*)d_in[4];
    const float* b_c    = (const float*)d_in[5];
    const float* W_root = (const float*)d_in[6];
    const float* b_root = (const float*)d_in[7];
    const float* W_rel  = (const float*)d_in[8];
    const int* src_pc = (const int*)d_in[9];
    const int* dst_pc = (const int*)d_in[10];
    const int* src_cp = (const int*)d_in[11];
    const int* dst_cp = (const int*)d_in[12];
    float* out = (float*)d_out;

    float *buf0, *buf1, *agg, *rcnt, *Bg;
    int *deg, *off, *cur, *csr;
    cudaGetSymbolAddress((void**)&buf0, g_buf0);
    cudaGetSymbolAddress((void**)&buf1, g_buf1);
    cudaGetSymbolAddress((void**)&agg,  g_agg);
    cudaGetSymbolAddress((void**)&rcnt, g_rcnt);
    cudaGetSymbolAddress((void**)&deg,  g_deg);
    cudaGetSymbolAddress((void**)&off,  g_off);
    cudaGetSymbolAddress((void**)&cur,  g_cur);
    cudaGetSymbolAddress((void**)&csr,  g_csr);
    cudaGetSymbolAddress((void**)&Bg,   g_B);

    const int PROJ64_SMEM  = (64  * 128 + 64 * 64 ) * 4;
    const int PROJ128_SMEM = (128 * 128 + 64 * 128) * 4;
    const int LAYER_SMEM   = SM_FLOATS * 4;              // ~71.7 KB
    cudaFuncSetAttribute(proj_kernel<64>,  cudaFuncAttributeMaxDynamicSharedMemorySize, PROJ64_SMEM);
    cudaFuncSetAttribute(proj_kernel<128>, cudaFuncAttributeMaxDynamicSharedMemorySize, PROJ128_SMEM);
    cudaFuncSetAttribute(layer_mma_kernel, cudaFuncAttributeMaxDynamicSharedMemorySize, LAYER_SMEM);

    // ---- CSR build ----
    cudaMemsetAsync(deg, 0, NN * sizeof(int));
    cudaMemsetAsync(cur, 0, NN * sizeof(int));
    deg_kernel<<<(2 * EE + 255) / 256, 256>>>(dst_pc, dst_cp, deg);
    scan_kernel<<<1, 1024>>>(deg, off);
    rcnt_kernel<<<(NN + 255) / 256, 256>>>(deg, rcnt);
    fill_kernel<<<(2 * EE + 255) / 256, 256>>>(src_pc, dst_pc, src_cp, dst_cp, off, cur, csr);

    // ---- weight prep ----
    prepB_kernel<<<(4 * 256 * 128 + 255) / 256, 256>>>(W_root, W_rel, Bg);

    // ---- projections ----
    proj_kernel<64><<<(NPAT + 63) / 64, 256, PROJ64_SMEM>>>(x_patient, W_p, b_p, buf0, NPAT);
    proj_kernel<128><<<(NCON + 63) / 64, 256, PROJ128_SMEM>>>(x_concept, W_c, b_c,
                                                              buf0 + (size_t)NPAT * HH, NCON);

    const int NB_TC = (NPAT + 127) / 128 + (NCON + 127) / 128;  // 391 + 157 = 548
    const int GATHER_BLOCKS = (NN + 7) / 8;

    for (int l = 0; l < LL; l++) {
        const float* in  = (l == 0) ? buf0 : buf1;
        float*       dst = (l == 0) ? buf1 : out;
        gather_kernel<<<GATHER_BLOCKS, 256>>>(in, off, csr, rcnt, agg);
        layer_mma_kernel<<<NB_TC, 256, LAYER_SMEM>>>(in, agg, Bg,
                                                     b_root + (size_t)l * HH, dst, l);
    }
}

// round 9
// speedup vs baseline: 1.2960x; 1.1049x over previous
#include <cuda_runtime.h>
#include <cuda_bf16.h>
#include <cstdint>

#define NPAT 50000
#define NCON 20000
#define NN   70000
#define EE   800000
#define HH   128
#define LL   2

// ---------------- scratch (static device globals; no allocs allowed) ----------------
__device__ float g_buf0[(size_t)NN * HH];
__device__ float g_buf1[(size_t)NN * HH];
__device__ float g_agg [(size_t)NN * HH];
__device__ int   g_deg [NN];
__device__ float g_rcnt[NN];
__device__ int   g_off [NN + 1];
__device__ int   g_cur [NN];
__device__ int   g_csr [2 * EE];
// pre-transposed/split weights: [variant(4)*split(2)][k(256)][n(128)]
__device__ float g_B[(size_t)8 * 256 * 128];

// ---------------- helpers ----------------
__device__ __forceinline__ float cvt_tf32(float v) {
    float h; asm("cvt.rna.tf32.f32 %0, %1;" : "=f"(h) : "f"(v)); return h;
}

__device__ __forceinline__ void mma_tf32(float* c, const uint32_t* a, const uint32_t* b) {
    asm volatile(
        "mma.sync.aligned.m16n8k8.row.col.f32.tf32.tf32.f32 "
        "{%0,%1,%2,%3}, {%4,%5,%6,%7}, {%8,%9}, {%0,%1,%2,%3};"
        : "+f"(c[0]), "+f"(c[1]), "+f"(c[2]), "+f"(c[3])
        : "r"(a[0]), "r"(a[1]), "r"(a[2]), "r"(a[3]),
          "r"(b[0]), "r"(b[1]));
}

// ---------------- degree histogram ----------------
__global__ void deg_kernel(const int* __restrict__ dst_pc, const int* __restrict__ dst_cp,
                           int* __restrict__ deg) {
    int i = blockIdx.x * blockDim.x + threadIdx.x;
    if (i < EE)               atomicAdd(&deg[NPAT + dst_pc[i]], 1);
    else if (i < 2 * EE)      atomicAdd(&deg[dst_cp[i - EE]], 1);
}

__global__ void rcnt_kernel(const int* __restrict__ deg, float* __restrict__ rcnt) {
    int i = blockIdx.x * blockDim.x + threadIdx.x;
    if (i < NN) rcnt[i] = 1.0f / (float)max(deg[i], 1);
}

// ---------------- single-block exclusive scan ----------------
__global__ void scan_kernel(const int* __restrict__ deg, int* __restrict__ off) {
    __shared__ int ssum[1024];
    int tid = threadIdx.x;
    const int PER = (NN + 1023) / 1024;
    int base = tid * PER;
    int s = 0;
    for (int i = 0; i < PER; i++) { int idx = base + i; if (idx < NN) s += deg[idx]; }
    ssum[tid] = s;
    __syncthreads();
    for (int ofs = 1; ofs < 1024; ofs <<= 1) {
        int v = (tid >= ofs) ? ssum[tid - ofs] : 0;
        __syncthreads();
        ssum[tid] += v;
        __syncthreads();
    }
    int run = (tid == 0) ? 0 : ssum[tid - 1];
    for (int i = 0; i < PER; i++) {
        int idx = base + i;
        if (idx < NN) { off[idx] = run; run += deg[idx]; }
    }
    if (tid == 0) off[NN] = ssum[1023];
}

// ---------------- CSR fill ----------------
__global__ void fill_kernel(const int* __restrict__ src_pc, const int* __restrict__ dst_pc,
                            const int* __restrict__ src_cp, const int* __restrict__ dst_cp,
                            const int* __restrict__ off, int* __restrict__ cur,
                            int* __restrict__ csr) {
    int i = blockIdx.x * blockDim.x + threadIdx.x;
    int s, d;
    if (i < EE)          { s = src_pc[i];             d = NPAT + dst_pc[i]; }
    else if (i < 2 * EE) { s = NPAT + src_cp[i - EE]; d = dst_cp[i - EE]; }
    else return;
    int pos = off[d] + atomicAdd(&cur[d], 1);
    csr[pos] = s;
}

// ---------------- gather-aggregate ----------------
__global__ void gather_kernel(const float* __restrict__ X,
                              const int* __restrict__ off, const int* __restrict__ csr,
                              const float* __restrict__ rcnt, float* __restrict__ AGG) {
    int warp = (int)((blockIdx.x * (long long)blockDim.x + threadIdx.x) >> 5);
    if (warp >= NN) return;
    int lane = threadIdx.x & 31;
    int beg = off[warp], end = off[warp + 1];
    float4 acc = make_float4(0.f, 0.f, 0.f, 0.f);
    int e = beg;
    for (; e + 32 <= end; e += 32) {
        int idx = csr[e + lane];
#pragma unroll
        for (int j = 0; j < 32; j++) {
            int s = __shfl_sync(0xffffffffu, idx, j);
            float4 v = ((const float4*)(X + (size_t)s * HH))[lane];
            acc.x += v.x; acc.y += v.y; acc.z += v.z; acc.w += v.w;
        }
    }
    int rem = end - e;
    if (rem > 0) {
        int idx = (lane < rem) ? csr[e + lane] : 0;
        for (int j = 0; j < rem; j++) {
            int s = __shfl_sync(0xffffffffu, idx, j);
            float4 v = ((const float4*)(X + (size_t)s * HH))[lane];
            acc.x += v.x; acc.y += v.y; acc.z += v.z; acc.w += v.w;
        }
    }
    float rc = rcnt[warp];
    ((float4*)(AGG + (size_t)warp * HH))[lane] =
        make_float4(acc.x * rc, acc.y * rc, acc.z * rc, acc.w * rc);
}

// ---------------- input projection (FFMA): C[M,128] = A[M,K] @ W[K,128] + b ---------
template <int K>
__global__ void proj_kernel(const float* __restrict__ A, const float* __restrict__ W,
                            const float* __restrict__ bias, float* __restrict__ C, int M) {
    extern __shared__ float sm[];
    float* sW = sm;
    float* sA = sm + K * 128;
    int tid = threadIdx.x;

    float4* sW4 = (float4*)sW;
    const float4* Wg = (const float4*)W;
    for (int i = tid; i < K * 32; i += 256) sW4[i] = Wg[i];
    {
        int row = tid >> 2, q = tid & 3;
        int r = blockIdx.x * 64 + row;
        const int f4p = K / 16;
        float4* dst = (float4*)(sA + row * K) + q * f4p;
        if (r < M) {
            const float4* Ar = (const float4*)(A + (size_t)r * K) + q * f4p;
#pragma unroll
            for (int i = 0; i < f4p; i++) dst[i] = Ar[i];
        } else {
#pragma unroll
            for (int i = 0; i < f4p; i++) dst[i] = make_float4(0.f, 0.f, 0.f, 0.f);
        }
    }
    __syncthreads();

    int rg = tid >> 5, cg = tid & 31;
    float4 acc[8];
#pragma unroll
    for (int i = 0; i < 8; i++) acc[i] = make_float4(0.f, 0.f, 0.f, 0.f);
    const float4* sA4 = (const float4*)sA;
#pragma unroll 2
    for (int k4 = 0; k4 < K / 4; k4++) {
        float4 w0 = sW4[(4 * k4 + 0) * 32 + cg];
        float4 w1 = sW4[(4 * k4 + 1) * 32 + cg];
        float4 w2 = sW4[(4 * k4 + 2) * 32 + cg];
        float4 w3 = sW4[(4 * k4 + 3) * 32 + cg];
#pragma unroll
        for (int i = 0; i < 8; i++) {
            float4 a = sA4[(rg * 8 + i) * (K / 4) + k4];
            acc[i].x += a.x * w0.x + a.y * w1.x + a.z * w2.x + a.w * w3.x;
            acc[i].y += a.x * w0.y + a.y * w1.y + a.z * w2.y + a.w * w3.y;
            acc[i].z += a.x * w0.z + a.y * w1.z + a.z * w2.z + a.w * w3.z;
            acc[i].w += a.x * w0.w + a.y * w1.w + a.z * w2.w + a.w * w3.w;
        }
    }
    float4 bb = ((const float4*)bias)[cg];
#pragma unroll
    for (int i = 0; i < 8; i++) {
        int r = blockIdx.x * 64 + rg * 8 + i;
        if (r < M) {
            float4 v = make_float4(acc[i].x + bb.x, acc[i].y + bb.y,
                                   acc[i].z + bb.z, acc[i].w + bb.w);
            ((float4*)(C + (size_t)r * HH))[cg] = v;
        }
    }
}

// ---------------- weight prep: transpose + tf32-split ------------------------------
// variant v: l = v>>1, type = v&1 (0 = patient rows -> [Wroot;Wrel[1]]; 1 = concept -> Wrel[0])
__global__ void prepB_kernel(const float* __restrict__ W_root, const float* __restrict__ W_rel,
                             float* __restrict__ B) {
    int i = blockIdx.x * blockDim.x + threadIdx.x;
    if (i >= 4 * 256 * 128) return;
    int n = i & 127;
    int k = (i >> 7) & 255;
    int v = i >> 15;
    int l = v >> 1, type = v & 1;
    float val;
    if (k < 128) {
        val = W_root[((size_t)l * 128 + k) * 128 + n];
    } else {
        int rel = (type == 0) ? 1 : 0;
        val = W_rel[(((size_t)l * 2 + rel) * 128 + (k - 128)) * 128 + n];
    }
    float hi = cvt_tf32(val);
    float lo = val - hi;
    B[(((size_t)(v * 2 + 0)) * 256 + k) * 128 + n] = hi;
    B[(((size_t)(v * 2 + 1)) * 256 + k) * 128 + n] = lo;
}

// ---------------- mma.sync tf32 layer: out = relu([x|agg] @ Bv + b) ------------------
// 2-split: A rounded to tf32 (single image), B kept exact as hi+lo.
// CTA: M=128, N=128, K=256 in 8 chunks of 32. 8 warps: warpM = wid&3, warpN = wid>>2.
#define ASTR 36
#define BSTR 136
#define SM_AHI 0
#define SM_BHI (128 * ASTR)
#define SM_BLO (128 * ASTR + 32 * BSTR)
#define SM_FLOATS (128 * ASTR + 2 * 32 * BSTR)   // 4608 + 8704 = 13312 floats (53.2 KB)

__global__ void __launch_bounds__(256, 2)
layer_mma_kernel(const float* __restrict__ X, const float* __restrict__ AGG,
                 const float* __restrict__ Bglob, const float* __restrict__ bias,
                 float* __restrict__ C, int layer) {
    extern __shared__ float sm[];
    int tid = threadIdx.x, wid = tid >> 5, lane = tid & 31;
    int warpM = wid & 3, warpN = wid >> 2;

    const int NBP_T = (NPAT + 127) / 128;   // 391
    int bid = blockIdx.x;
    int base, rowlim, v;
    if (bid < NBP_T) { base = bid * 128;                  rowlim = NPAT; v = layer * 2; }
    else             { base = NPAT + (bid - NBP_T) * 128; rowlim = NN;   v = layer * 2 + 1; }

    float acc[2][8][4];
#pragma unroll
    for (int mt = 0; mt < 2; mt++)
#pragma unroll
        for (int nt = 0; nt < 8; nt++)
#pragma unroll
            for (int r = 0; r < 4; r++) acc[mt][nt][r] = 0.f;

    int arow = tid >> 1;
    int node = base + arow;
    bool valid = node < rowlim;
    int f4base = (tid & 1) * 4;

    for (int chunk = 0; chunk < 8; chunk++) {
        const float* src = (chunk < 4)
            ? (X   + (size_t)node * HH + chunk * 32)
            : (AGG + (size_t)node * HH + (chunk - 4) * 32);
#pragma unroll
        for (int i = 0; i < 4; i++) {
            int f4 = f4base + i;
            float4 a = valid ? ((const float4*)src)[f4] : make_float4(0.f, 0.f, 0.f, 0.f);
            float4 hi4;
            hi4.x = cvt_tf32(a.x);
            hi4.y = cvt_tf32(a.y);
            hi4.z = cvt_tf32(a.z);
            hi4.w = cvt_tf32(a.w);
            *(float4*)&sm[SM_AHI + arow * ASTR + f4 * 4] = hi4;
        }
        {
            const float4* bh = (const float4*)(Bglob + (((size_t)(v * 2 + 0)) * 256 + chunk * 32) * 128);
            const float4* bl = (const float4*)(Bglob + (((size_t)(v * 2 + 1)) * 256 + chunk * 32) * 128);
#pragma unroll
            for (int i = 0; i < 4; i++) {
                int idx = tid + 256 * i;          // < 1024
                int kk = idx >> 5, n4 = idx & 31;
                *(float4*)&sm[SM_BHI + kk * BSTR + n4 * 4] = bh[idx];
                *(float4*)&sm[SM_BLO + kk * BSTR + n4 * 4] = bl[idx];
            }
        }
        __syncthreads();

#pragma unroll
        for (int k8 = 0; k8 < 4; k8++) {
            int k0 = k8 * 8;
            uint32_t ah[2][4];
#pragma unroll
            for (int mt = 0; mt < 2; mt++) {
                int r0 = warpM * 32 + mt * 16 + (lane >> 2);
                int c0 = k0 + (lane & 3);
                ah[mt][0] = __float_as_uint(sm[SM_AHI + r0 * ASTR + c0]);
                ah[mt][1] = __float_as_uint(sm[SM_AHI + (r0 + 8) * ASTR + c0]);
                ah[mt][2] = __float_as_uint(sm[SM_AHI + r0 * ASTR + c0 + 4]);
                ah[mt][3] = __float_as_uint(sm[SM_AHI + (r0 + 8) * ASTR + c0 + 4]);
            }
#pragma unroll
            for (int nt = 0; nt < 8; nt++) {
                int n = warpN * 64 + nt * 8 + (lane >> 2);
                int kr = k0 + (lane & 3);
                uint32_t bh[2], bl[2];
                bh[0] = __float_as_uint(sm[SM_BHI + kr * BSTR + n]);
                bh[1] = __float_as_uint(sm[SM_BHI + (kr + 4) * BSTR + n]);
                bl[0] = __float_as_uint(sm[SM_BLO + kr * BSTR + n]);
                bl[1] = __float_as_uint(sm[SM_BLO + (kr + 4) * BSTR + n]);
#pragma unroll
                for (int mt = 0; mt < 2; mt++) {
                    mma_tf32(acc[mt][nt], ah[mt], bh);
                    mma_tf32(acc[mt][nt], ah[mt], bl);
                }
            }
        }
        __syncthreads();
    }

    // ---- epilogue: bias + relu, direct global stores ----
#pragma unroll
    for (int mt = 0; mt < 2; mt++) {
        int row = base + warpM * 32 + mt * 16 + (lane >> 2);
#pragma unroll
        for (int nt = 0; nt < 8; nt++) {
            int col = warpN * 64 + nt * 8 + (lane & 3) * 2;
            float2 bv = *(const float2*)&bias[col];
            if (row < rowlim) {
                float2 o;
                o.x = fmaxf(acc[mt][nt][0] + bv.x, 0.f);
                o.y = fmaxf(acc[mt][nt][1] + bv.y, 0.f);
                *(float2*)&C[(size_t)row * HH + col] = o;
            }
            if (row + 8 < rowlim) {
                float2 o;
                o.x = fmaxf(acc[mt][nt][2] + bv.x, 0.f);
                o.y = fmaxf(acc[mt][nt][3] + bv.y, 0.f);
                *(float2*)&C[(size_t)(row + 8) * HH + col] = o;
            }
        }
    }
}

// ---------------- launch ----------------
extern "C" void kernel_launch(void* const* d_in, const int* in_sizes, int n_in,
                              void* d_out, int out_size) {
    const float* x_patient = (const float*)d_in[0];
    const float* x_concept = (const float*)d_in[1];
    const float* W_p    = (const float*)d_in[2];
    const float* b_p    = (const float*)d_in[3];
    const float* W_c    = (const float*)d_in[4];
    const float* b_c    = (const float*)d_in[5];
    const float* W_root = (const float*)d_in[6];
    const float* b_root = (const float*)d_in[7];
    const float* W_rel  = (const float*)d_in[8];
    const int* src_pc = (const int*)d_in[9];
    const int* dst_pc = (const int*)d_in[10];
    const int* src_cp = (const int*)d_in[11];
    const int* dst_cp = (const int*)d_in[12];
    float* out = (float*)d_out;

    float *buf0, *buf1, *agg, *rcnt, *Bg;
    int *deg, *off, *cur, *csr;
    cudaGetSymbolAddress((void**)&buf0, g_buf0);
    cudaGetSymbolAddress((void**)&buf1, g_buf1);
    cudaGetSymbolAddress((void**)&agg,  g_agg);
    cudaGetSymbolAddress((void**)&rcnt, g_rcnt);
    cudaGetSymbolAddress((void**)&deg,  g_deg);
    cudaGetSymbolAddress((void**)&off,  g_off);
    cudaGetSymbolAddress((void**)&cur,  g_cur);
    cudaGetSymbolAddress((void**)&csr,  g_csr);
    cudaGetSymbolAddress((void**)&Bg,   g_B);

    const int PROJ64_SMEM  = (64  * 128 + 64 * 64 ) * 4;
    const int PROJ128_SMEM = (128 * 128 + 64 * 128) * 4;
    const int LAYER_SMEM   = SM_FLOATS * 4;              // 53.2 KB
    cudaFuncSetAttribute(proj_kernel<64>,  cudaFuncAttributeMaxDynamicSharedMemorySize, PROJ64_SMEM);
    cudaFuncSetAttribute(proj_kernel<128>, cudaFuncAttributeMaxDynamicSharedMemorySize, PROJ128_SMEM);
    cudaFuncSetAttribute(layer_mma_kernel, cudaFuncAttributeMaxDynamicSharedMemorySize, LAYER_SMEM);

    // ---- CSR build ----
    cudaMemsetAsync(deg, 0, NN * sizeof(int));
    cudaMemsetAsync(cur, 0, NN * sizeof(int));
    deg_kernel<<<(2 * EE + 255) / 256, 256>>>(dst_pc, dst_cp, deg);
    scan_kernel<<<1, 1024>>>(deg, off);
    rcnt_kernel<<<(NN + 255) / 256, 256>>>(deg, rcnt);
    fill_kernel<<<(2 * EE + 255) / 256, 256>>>(src_pc, dst_pc, src_cp, dst_cp, off, cur, csr);

    // ---- weight prep ----
    prepB_kernel<<<(4 * 256 * 128 + 255) / 256, 256>>>(W_root, W_rel, Bg);

    // ---- projections ----
    proj_kernel<64><<<(NPAT + 63) / 64, 256, PROJ64_SMEM>>>(x_patient, W_p, b_p, buf0, NPAT);
    proj_kernel<128><<<(NCON + 63) / 64, 256, PROJ128_SMEM>>>(x_concept, W_c, b_c,
                                                              buf0 + (size_t)NPAT * HH, NCON);

    const int NB_TC = (NPAT + 127) / 128 + (NCON + 127) / 128;  // 391 + 157 = 548
    const int GATHER_BLOCKS = (NN + 7) / 8;

    for (int l = 0; l < LL; l++) {
        const float* in  = (l == 0) ? buf0 : buf1;
        float*       dst = (l == 0) ? buf1 : out;
        gather_kernel<<<GATHER_BLOCKS, 256>>>(in, off, csr, rcnt, agg);
        layer_mma_kernel<<<NB_TC, 256, LAYER_SMEM>>>(in, agg, Bg,
                                                     b_root + (size_t)l * HH, dst, l);
    }
}

// round 11
// speedup vs baseline: 1.4392x; 1.1105x over previous
#include <cuda_runtime.h>
#include <cuda_fp16.h>
#include <cstdint>

#define NPAT 50000
#define NCON 20000
#define NN   70000
#define EE   800000
#define HH   128
#define LL   2

// ---------------- scratch (static device globals; no allocs allowed) ----------------
// Activations stored ONLY in fp16 (10-bit mantissa == tf32 mantissa; the layer GEMM
// rounded A to tf32 anyway). Replaces fp32 buffers -> L2 working set ~62 MB.
__device__ __half g_h0   [(size_t)NN * HH];   // proj output / layer-0 input
__device__ __half g_h1   [(size_t)NN * HH];   // layer-0 output / layer-1 input
__device__ __half g_agg16[(size_t)NN * HH];   // neighbor mean (fp32 accum, fp16 store)
__device__ int    g_deg [NN];
__device__ float  g_rcnt[NN];
__device__ int    g_off [NN + 1];
__device__ int    g_cur [NN];
__device__ int    g_csr [2 * EE];
// pre-transposed/split weights: [variant(4)*split(2)][k(256)][n(128)]
__device__ float g_B[(size_t)8 * 256 * 128];

// ---------------- helpers ----------------
__device__ __forceinline__ float cvt_tf32(float v) {
    float h; asm("cvt.rna.tf32.f32 %0, %1;" : "=f"(h) : "f"(v)); return h;
}

__device__ __forceinline__ void mma_tf32(float* c, const uint32_t* a, const uint32_t* b) {
    asm volatile(
        "mma.sync.aligned.m16n8k8.row.col.f32.tf32.tf32.f32 "
        "{%0,%1,%2,%3}, {%4,%5,%6,%7}, {%8,%9}, {%0,%1,%2,%3};"
        : "+f"(c[0]), "+f"(c[1]), "+f"(c[2]), "+f"(c[3])
        : "r"(a[0]), "r"(a[1]), "r"(a[2]), "r"(a[3]),
          "r"(b[0]), "r"(b[1]));
}

// ---------------- degree histogram ----------------
__global__ void deg_kernel(const int* __restrict__ dst_pc, const int* __restrict__ dst_cp,
                           int* __restrict__ deg) {
    int i = blockIdx.x * blockDim.x + threadIdx.x;
    if (i < EE)               atomicAdd(&deg[NPAT + dst_pc[i]], 1);
    else if (i < 2 * EE)      atomicAdd(&deg[dst_cp[i - EE]], 1);
}

__global__ void rcnt_kernel(const int* __restrict__ deg, float* __restrict__ rcnt) {
    int i = blockIdx.x * blockDim.x + threadIdx.x;
    if (i < NN) rcnt[i] = 1.0f / (float)max(deg[i], 1);
}

// ---------------- single-block exclusive scan ----------------
__global__ void scan_kernel(const int* __restrict__ deg, int* __restrict__ off) {
    __shared__ int ssum[1024];
    int tid = threadIdx.x;
    const int PER = (NN + 1023) / 1024;
    int base = tid * PER;
    int s = 0;
    for (int i = 0; i < PER; i++) { int idx = base + i; if (idx < NN) s += deg[idx]; }
    ssum[tid] = s;
    __syncthreads();
    for (int ofs = 1; ofs < 1024; ofs <<= 1) {
        int v = (tid >= ofs) ? ssum[tid - ofs] : 0;
        __syncthreads();
        ssum[tid] += v;
        __syncthreads();
    }
    int run = (tid == 0) ? 0 : ssum[tid - 1];
    for (int i = 0; i < PER; i++) {
        int idx = base + i;
        if (idx < NN) { off[idx] = run; run += deg[idx]; }
    }
    if (tid == 0) off[NN] = ssum[1023];
}

// ---------------- CSR fill ----------------
__global__ void fill_kernel(const int* __restrict__ src_pc, const int* __restrict__ dst_pc,
                            const int* __restrict__ src_cp, const int* __restrict__ dst_cp,
                            const int* __restrict__ off, int* __restrict__ cur,
                            int* __restrict__ csr) {
    int i = blockIdx.x * blockDim.x + threadIdx.x;
    int s, d;
    if (i < EE)          { s = src_pc[i];             d = NPAT + dst_pc[i]; }
    else if (i < 2 * EE) { s = NPAT + src_cp[i - EE]; d = dst_cp[i - EE]; }
    else return;
    int pos = off[d] + atomicAdd(&cur[d], 1);
    csr[pos] = s;
}

// ---------------- fp16 gather-aggregate (fp32 accumulate, fp16 store) ---------------
__global__ void gather_kernel(const __half* __restrict__ X16,
                              const int* __restrict__ off, const int* __restrict__ csr,
                              const float* __restrict__ rcnt, __half* __restrict__ AGG16) {
    int warp = (int)((blockIdx.x * (long long)blockDim.x + threadIdx.x) >> 5);
    if (warp >= NN) return;
    int lane = threadIdx.x & 31;
    int beg = off[warp], end = off[warp + 1];
    float4 acc = make_float4(0.f, 0.f, 0.f, 0.f);
    int e = beg;
    for (; e + 32 <= end; e += 32) {
        int idx = csr[e + lane];
#pragma unroll
        for (int j = 0; j < 32; j++) {
            int s = __shfl_sync(0xffffffffu, idx, j);
            uint2 u = ((const uint2*)(X16 + (size_t)s * HH))[lane];
            float2 f0 = __half22float2(*(__half2*)&u.x);
            float2 f1 = __half22float2(*(__half2*)&u.y);
            acc.x += f0.x; acc.y += f0.y; acc.z += f1.x; acc.w += f1.y;
        }
    }
    int rem = end - e;
    if (rem > 0) {
        int idx = (lane < rem) ? csr[e + lane] : 0;
        for (int j = 0; j < rem; j++) {
            int s = __shfl_sync(0xffffffffu, idx, j);
            uint2 u = ((const uint2*)(X16 + (size_t)s * HH))[lane];
            float2 f0 = __half22float2(*(__half2*)&u.x);
            float2 f1 = __half22float2(*(__half2*)&u.y);
            acc.x += f0.x; acc.y += f0.y; acc.z += f1.x; acc.w += f1.y;
        }
    }
    float rc = rcnt[warp];
    uint2 o;
    *(__half2*)&o.x = __floats2half2_rn(acc.x * rc, acc.y * rc);
    *(__half2*)&o.y = __floats2half2_rn(acc.z * rc, acc.w * rc);
    ((uint2*)(AGG16 + (size_t)warp * HH))[lane] = o;
}

// ---------------- input projection (FFMA) -> fp16 output ----------------------------
template <int K>
__global__ void proj_kernel(const float* __restrict__ A, const float* __restrict__ W,
                            const float* __restrict__ bias, __half* __restrict__ CH, int M) {
    extern __shared__ float sm[];
    float* sW = sm;
    float* sA = sm + K * 128;
    int tid = threadIdx.x;

    float4* sW4 = (float4*)sW;
    const float4* Wg = (const float4*)W;
    for (int i = tid; i < K * 32; i += 256) sW4[i] = Wg[i];
    {
        int row = tid >> 2, q = tid & 3;
        int r = blockIdx.x * 64 + row;
        const int f4p = K / 16;
        float4* dst = (float4*)(sA + row * K) + q * f4p;
        if (r < M) {
            const float4* Ar = (const float4*)(A + (size_t)r * K) + q * f4p;
#pragma unroll
            for (int i = 0; i < f4p; i++) dst[i] = Ar[i];
        } else {
#pragma unroll
            for (int i = 0; i < f4p; i++) dst[i] = make_float4(0.f, 0.f, 0.f, 0.f);
        }
    }
    __syncthreads();

    int rg = tid >> 5, cg = tid & 31;
    float4 acc[8];
#pragma unroll
    for (int i = 0; i < 8; i++) acc[i] = make_float4(0.f, 0.f, 0.f, 0.f);
    const float4* sA4 = (const float4*)sA;
#pragma unroll 2
    for (int k4 = 0; k4 < K / 4; k4++) {
        float4 w0 = sW4[(4 * k4 + 0) * 32 + cg];
        float4 w1 = sW4[(4 * k4 + 1) * 32 + cg];
        float4 w2 = sW4[(4 * k4 + 2) * 32 + cg];
        float4 w3 = sW4[(4 * k4 + 3) * 32 + cg];
#pragma unroll
        for (int i = 0; i < 8; i++) {
            float4 a = sA4[(rg * 8 + i) * (K / 4) + k4];
            acc[i].x += a.x * w0.x + a.y * w1.x + a.z * w2.x + a.w * w3.x;
            acc[i].y += a.x * w0.y + a.y * w1.y + a.z * w2.y + a.w * w3.y;
            acc[i].z += a.x * w0.z + a.y * w1.z + a.z * w2.z + a.w * w3.z;
            acc[i].w += a.x * w0.w + a.y * w1.w + a.z * w2.w + a.w * w3.w;
        }
    }
    float4 bb = ((const float4*)bias)[cg];
#pragma unroll
    for (int i = 0; i < 8; i++) {
        int r = blockIdx.x * 64 + rg * 8 + i;
        if (r < M) {
            uint2 h;
            *(__half2*)&h.x = __floats2half2_rn(acc[i].x + bb.x, acc[i].y + bb.y);
            *(__half2*)&h.y = __floats2half2_rn(acc[i].z + bb.z, acc[i].w + bb.w);
            ((uint2*)(CH + (size_t)r * HH))[cg] = h;
        }
    }
}

// ---------------- weight prep: transpose + tf32-split ------------------------------
__global__ void prepB_kernel(const float* __restrict__ W_root, const float* __restrict__ W_rel,
                             float* __restrict__ B) {
    int i = blockIdx.x * blockDim.x + threadIdx.x;
    if (i >= 4 * 256 * 128) return;
    int n = i & 127;
    int k = (i >> 7) & 255;
    int v = i >> 15;
    int l = v >> 1, type = v & 1;
    float val;
    if (k < 128) {
        val = W_root[((size_t)l * 128 + k) * 128 + n];
    } else {
        int rel = (type == 0) ? 1 : 0;
        val = W_rel[(((size_t)l * 2 + rel) * 128 + (k - 128)) * 128 + n];
    }
    float hi = cvt_tf32(val);
    float lo = val - hi;
    B[(((size_t)(v * 2 + 0)) * 256 + k) * 128 + n] = hi;
    B[(((size_t)(v * 2 + 1)) * 256 + k) * 128 + n] = lo;
}

// ---------------- mma.sync tf32 layer: out = relu([x|agg] @ Bv + b) ------------------
// A read from fp16 (exact->fp32, already tf32-representable); B exact hi+lo 2-split.
#define ASTR 36
#define BSTR 136
#define SM_AHI 0
#define SM_BHI (128 * ASTR)
#define SM_BLO (128 * ASTR + 32 * BSTR)
#define SM_FLOATS (128 * ASTR + 2 * 32 * BSTR)   // 13312 floats (53.2 KB)

template <bool FINAL>
__global__ void __launch_bounds__(256, 2)
layer_mma_kernel(const __half* __restrict__ X16, const __half* __restrict__ AGG16,
                 const float* __restrict__ Bglob, const float* __restrict__ bias,
                 float* __restrict__ C, __half* __restrict__ CH, int layer) {
    extern __shared__ float sm[];
    int tid = threadIdx.x, wid = tid >> 5, lane = tid & 31;
    int warpM = wid & 3, warpN = wid >> 2;

    const int NBP_T = (NPAT + 127) / 128;   // 391
    int bid = blockIdx.x;
    int base, rowlim, v;
    if (bid < NBP_T) { base = bid * 128;                  rowlim = NPAT; v = layer * 2; }
    else             { base = NPAT + (bid - NBP_T) * 128; rowlim = NN;   v = layer * 2 + 1; }

    float acc[2][8][4];
#pragma unroll
    for (int mt = 0; mt < 2; mt++)
#pragma unroll
        for (int nt = 0; nt < 8; nt++)
#pragma unroll
            for (int r = 0; r < 4; r++) acc[mt][nt][r] = 0.f;

    int arow = tid >> 1;
    int node = base + arow;
    bool valid = node < rowlim;
    int f4base = (tid & 1) * 4;

    for (int chunk = 0; chunk < 8; chunk++) {
        const __half* src = (chunk < 4)
            ? (X16   + (size_t)node * HH + chunk * 32)
            : (AGG16 + (size_t)node * HH + (chunk - 4) * 32);
#pragma unroll
        for (int i = 0; i < 4; i++) {
            int f4 = f4base + i;
            uint2 u = valid ? ((const uint2*)src)[f4] : make_uint2(0u, 0u);
            float2 f0 = __half22float2(*(__half2*)&u.x);
            float2 f1 = __half22float2(*(__half2*)&u.y);
            *(float4*)&sm[SM_AHI + arow * ASTR + f4 * 4] = make_float4(f0.x, f0.y, f1.x, f1.y);
        }
        {
            const float4* bh = (const float4*)(Bglob + (((size_t)(v * 2 + 0)) * 256 + chunk * 32) * 128);
            const float4* bl = (const float4*)(Bglob + (((size_t)(v * 2 + 1)) * 256 + chunk * 32) * 128);
#pragma unroll
            for (int i = 0; i < 4; i++) {
                int idx = tid + 256 * i;          // < 1024
                int kk = idx >> 5, n4 = idx & 31;
                *(float4*)&sm[SM_BHI + kk * BSTR + n4 * 4] = bh[idx];
                *(float4*)&sm[SM_BLO + kk * BSTR + n4 * 4] = bl[idx];
            }
        }
        __syncthreads();

#pragma unroll
        for (int k8 = 0; k8 < 4; k8++) {
            int k0 = k8 * 8;
            uint32_t ah[2][4];
#pragma unroll
            for (int mt = 0; mt < 2; mt++) {
                int r0 = warpM * 32 + mt * 16 + (lane >> 2);
                int c0 = k0 + (lane & 3);
                ah[mt][0] = __float_as_uint(sm[SM_AHI + r0 * ASTR + c0]);
                ah[mt][1] = __float_as_uint(sm[SM_AHI + (r0 + 8) * ASTR + c0]);
                ah[mt][2] = __float_as_uint(sm[SM_AHI + r0 * ASTR + c0 + 4]);
                ah[mt][3] = __float_as_uint(sm[SM_AHI + (r0 + 8) * ASTR + c0 + 4]);
            }
#pragma unroll
            for (int nt = 0; nt < 8; nt++) {
                int n = warpN * 64 + nt * 8 + (lane >> 2);
                int kr = k0 + (lane & 3);
                uint32_t bh[2], bl[2];
                bh[0] = __float_as_uint(sm[SM_BHI + kr * BSTR + n]);
                bh[1] = __float_as_uint(sm[SM_BHI + (kr + 4) * BSTR + n]);
                bl[0] = __float_as_uint(sm[SM_BLO + kr * BSTR + n]);
                bl[1] = __float_as_uint(sm[SM_BLO + (kr + 4) * BSTR + n]);
#pragma unroll
                for (int mt = 0; mt < 2; mt++) {
                    mma_tf32(acc[mt][nt], ah[mt], bh);
                    mma_tf32(acc[mt][nt], ah[mt], bl);
                }
            }
        }
        __syncthreads();
    }

    // ---- epilogue: bias + relu ----
#pragma unroll
    for (int mt = 0; mt < 2; mt++) {
        int row = base + warpM * 32 + mt * 16 + (lane >> 2);
#pragma unroll
        for (int nt = 0; nt < 8; nt++) {
            int col = warpN * 64 + nt * 8 + (lane & 3) * 2;
            float2 bv = *(const float2*)&bias[col];
            if (row < rowlim) {
                float2 o;
                o.x = fmaxf(acc[mt][nt][0] + bv.x, 0.f);
                o.y = fmaxf(acc[mt][nt][1] + bv.y, 0.f);
                if (FINAL) *(float2*)&C[(size_t)row * HH + col] = o;
                else       *(__half2*)&CH[(size_t)row * HH + col] = __floats2half2_rn(o.x, o.y);
            }
            if (row + 8 < rowlim) {
                float2 o;
                o.x = fmaxf(acc[mt][nt][2] + bv.x, 0.f);
                o.y = fmaxf(acc[mt][nt][3] + bv.y, 0.f);
                if (FINAL) *(float2*)&C[(size_t)(row + 8) * HH + col] = o;
                else       *(__half2*)&CH[(size_t)(row + 8) * HH + col] = __floats2half2_rn(o.x, o.y);
            }
        }
    }
}

// ---------------- launch ----------------
extern "C" void kernel_launch(void* const* d_in, const int* in_sizes, int n_in,
                              void* d_out, int out_size) {
    const float* x_patient = (const float*)d_in[0];
    const float* x_concept = (const float*)d_in[1];
    const float* W_p    = (const float*)d_in[2];
    const float* b_p    = (const float*)d_in[3];
    const float* W_c    = (const float*)d_in[4];
    const float* b_c    = (const float*)d_in[5];
    const float* W_root = (const float*)d_in[6];
    const float* b_root = (const float*)d_in[7];
    const float* W_rel  = (const float*)d_in[8];
    const int* src_pc = (const int*)d_in[9];
    const int* dst_pc = (const int*)d_in[10];
    const int* src_cp = (const int*)d_in[11];
    const int* dst_cp = (const int*)d_in[12];
    float* out = (float*)d_out;

    float *rcnt, *Bg;
    __half *h0, *h1, *agg16;
    int *deg, *off, *cur, *csr;
    cudaGetSymbolAddress((void**)&h0,    g_h0);
    cudaGetSymbolAddress((void**)&h1,    g_h1);
    cudaGetSymbolAddress((void**)&agg16, g_agg16);
    cudaGetSymbolAddress((void**)&rcnt,  g_rcnt);
    cudaGetSymbolAddress((void**)&deg,   g_deg);
    cudaGetSymbolAddress((void**)&off,   g_off);
    cudaGetSymbolAddress((void**)&cur,   g_cur);
    cudaGetSymbolAddress((void**)&csr,   g_csr);
    cudaGetSymbolAddress((void**)&Bg,    g_B);

    const int PROJ64_SMEM  = (64  * 128 + 64 * 64 ) * 4;
    const int PROJ128_SMEM = (128 * 128 + 64 * 128) * 4;
    const int LAYER_SMEM   = SM_FLOATS * 4;              // 53.2 KB
    cudaFuncSetAttribute(proj_kernel<64>,  cudaFuncAttributeMaxDynamicSharedMemorySize, PROJ64_SMEM);
    cudaFuncSetAttribute(proj_kernel<128>, cudaFuncAttributeMaxDynamicSharedMemorySize, PROJ128_SMEM);
    cudaFuncSetAttribute(layer_mma_kernel<false>, cudaFuncAttributeMaxDynamicSharedMemorySize, LAYER_SMEM);
    cudaFuncSetAttribute(layer_mma_kernel<true>,  cudaFuncAttributeMaxDynamicSharedMemorySize, LAYER_SMEM);

    // ---- CSR build ----
    cudaMemsetAsync(deg, 0, NN * sizeof(int));
    cudaMemsetAsync(cur, 0, NN * sizeof(int));
    deg_kernel<<<(2 * EE + 255) / 256, 256>>>(dst_pc, dst_cp, deg);
    scan_kernel<<<1, 1024>>>(deg, off);
    rcnt_kernel<<<(NN + 255) / 256, 256>>>(deg, rcnt);
    fill_kernel<<<(2 * EE + 255) / 256, 256>>>(src_pc, dst_pc, src_cp, dst_cp, off, cur, csr);

    // ---- weight prep ----
    prepB_kernel<<<(4 * 256 * 128 + 255) / 256, 256>>>(W_root, W_rel, Bg);

    // ---- projections (fp32 FFMA compute, fp16 store) ----
    proj_kernel<64><<<(NPAT + 63) / 64, 256, PROJ64_SMEM>>>(x_patient, W_p, b_p, h0, NPAT);
    proj_kernel<128><<<(NCON + 63) / 64, 256, PROJ128_SMEM>>>(x_concept, W_c, b_c,
                                                              h0 + (size_t)NPAT * HH, NCON);

    const int NB_TC = (NPAT + 127) / 128 + (NCON + 127) / 128;  // 548
    const int GATHER_BLOCKS = (NN + 7) / 8;

    // ---- layer 0 (fp16 out) ----
    gather_kernel<<<GATHER_BLOCKS, 256>>>(h0, off, csr, rcnt, agg16);
    layer_mma_kernel<false><<<NB_TC, 256, LAYER_SMEM>>>(h0, agg16, Bg, b_root,
                                                        (float*)nullptr, h1, 0);
    // ---- layer 1 (fp32 out) ----
    gather_kernel<<<GATHER_BLOCKS, 256>>>(h1, off, csr, rcnt, agg16);
    layer_mma_kernel<true><<<NB_TC, 256, LAYER_SMEM>>>(h1, agg16, Bg, b_root + HH,
                                                       out, (__half*)nullptr, 1);
}

// round 12
// speedup vs baseline: 1.6369x; 1.1374x over previous
#include <cuda_runtime.h>
#include <cuda_fp16.h>
#include <cstdint>

#define NPAT 50000
#define NCON 20000
#define NN   70000
#define EE   800000
#define HH   128
#define LL   2

// ---------------- scratch (static device globals; no allocs allowed) ----------------
__device__ __half g_h0   [(size_t)NN * HH];   // proj output / layer-0 input
__device__ __half g_h1   [(size_t)NN * HH];   // layer-0 output / layer-1 input
__device__ __half g_agg16[(size_t)NN * HH];   // neighbor mean (fp32 accum, fp16 store)
__device__ int    g_deg [NN];
__device__ float  g_rcnt[NN];
__device__ int    g_off [NN + 1];
__device__ int    g_cur [NN];
__device__ int    g_csr [2 * EE];
// fp16 hi/lo split weights, half2-packed along k:
// half idx = ((vs*16384 + k2*128 + n)*2 + (k&1)), vs = variant*2 + split
__device__ __half g_B16[(size_t)8 * 128 * 128 * 2];

// ---------------- helpers ----------------
__device__ __forceinline__ void mma_f16(float* c, const uint32_t* a, const uint32_t* b) {
    asm volatile(
        "mma.sync.aligned.m16n8k16.row.col.f32.f16.f16.f32 "
        "{%0,%1,%2,%3}, {%4,%5,%6,%7}, {%8,%9}, {%0,%1,%2,%3};"
        : "+f"(c[0]), "+f"(c[1]), "+f"(c[2]), "+f"(c[3])
        : "r"(a[0]), "r"(a[1]), "r"(a[2]), "r"(a[3]),
          "r"(b[0]), "r"(b[1]));
}

// ---------------- degree histogram ----------------
__global__ void deg_kernel(const int* __restrict__ dst_pc, const int* __restrict__ dst_cp,
                           int* __restrict__ deg) {
    int i = blockIdx.x * blockDim.x + threadIdx.x;
    if (i < EE)               atomicAdd(&deg[NPAT + dst_pc[i]], 1);
    else if (i < 2 * EE)      atomicAdd(&deg[dst_cp[i - EE]], 1);
}

__global__ void rcnt_kernel(const int* __restrict__ deg, float* __restrict__ rcnt) {
    int i = blockIdx.x * blockDim.x + threadIdx.x;
    if (i < NN) rcnt[i] = 1.0f / (float)max(deg[i], 1);
}

// ---------------- single-block exclusive scan ----------------
__global__ void scan_kernel(const int* __restrict__ deg, int* __restrict__ off) {
    __shared__ int ssum[1024];
    int tid = threadIdx.x;
    const int PER = (NN + 1023) / 1024;
    int base = tid * PER;
    int s = 0;
    for (int i = 0; i < PER; i++) { int idx = base + i; if (idx < NN) s += deg[idx]; }
    ssum[tid] = s;
    __syncthreads();
    for (int ofs = 1; ofs < 1024; ofs <<= 1) {
        int v = (tid >= ofs) ? ssum[tid - ofs] : 0;
        __syncthreads();
        ssum[tid] += v;
        __syncthreads();
    }
    int run = (tid == 0) ? 0 : ssum[tid - 1];
    for (int i = 0; i < PER; i++) {
        int idx = base + i;
        if (idx < NN) { off[idx] = run; run += deg[idx]; }
    }
    if (tid == 0) off[NN] = ssum[1023];
}

// ---------------- CSR fill ----------------
__global__ void fill_kernel(const int* __restrict__ src_pc, const int* __restrict__ dst_pc,
                            const int* __restrict__ src_cp, const int* __restrict__ dst_cp,
                            const int* __restrict__ off, int* __restrict__ cur,
                            int* __restrict__ csr) {
    int i = blockIdx.x * blockDim.x + threadIdx.x;
    int s, d;
    if (i < EE)          { s = src_pc[i];             d = NPAT + dst_pc[i]; }
    else if (i < 2 * EE) { s = NPAT + src_cp[i - EE]; d = dst_cp[i - EE]; }
    else return;
    int pos = off[d] + atomicAdd(&cur[d], 1);
    csr[pos] = s;
}

// ---------------- fp16 gather-aggregate (fp32 accumulate, fp16 store) ---------------
__global__ void gather_kernel(const __half* __restrict__ X16,
                              const int* __restrict__ off, const int* __restrict__ csr,
                              const float* __restrict__ rcnt, __half* __restrict__ AGG16) {
    int warp = (int)((blockIdx.x * (long long)blockDim.x + threadIdx.x) >> 5);
    if (warp >= NN) return;
    int lane = threadIdx.x & 31;
    int beg = off[warp], end = off[warp + 1];
    float4 acc = make_float4(0.f, 0.f, 0.f, 0.f);
    int e = beg;
    for (; e + 32 <= end; e += 32) {
        int idx = csr[e + lane];
#pragma unroll
        for (int j = 0; j < 32; j++) {
            int s = __shfl_sync(0xffffffffu, idx, j);
            uint2 u = ((const uint2*)(X16 + (size_t)s * HH))[lane];
            float2 f0 = __half22float2(*(__half2*)&u.x);
            float2 f1 = __half22float2(*(__half2*)&u.y);
            acc.x += f0.x; acc.y += f0.y; acc.z += f1.x; acc.w += f1.y;
        }
    }
    int rem = end - e;
    if (rem > 0) {
        int idx = (lane < rem) ? csr[e + lane] : 0;
        for (int j = 0; j < rem; j++) {
            int s = __shfl_sync(0xffffffffu, idx, j);
            uint2 u = ((const uint2*)(X16 + (size_t)s * HH))[lane];
            float2 f0 = __half22float2(*(__half2*)&u.x);
            float2 f1 = __half22float2(*(__half2*)&u.y);
            acc.x += f0.x; acc.y += f0.y; acc.z += f1.x; acc.w += f1.y;
        }
    }
    float rc = rcnt[warp];
    uint2 o;
    *(__half2*)&o.x = __floats2half2_rn(acc.x * rc, acc.y * rc);
    *(__half2*)&o.y = __floats2half2_rn(acc.z * rc, acc.w * rc);
    ((uint2*)(AGG16 + (size_t)warp * HH))[lane] = o;
}

// ---------------- input projection (FFMA) -> fp16 output ----------------------------
template <int K>
__global__ void proj_kernel(const float* __restrict__ A, const float* __restrict__ W,
                            const float* __restrict__ bias, __half* __restrict__ CH, int M) {
    extern __shared__ float sm[];
    float* sW = sm;
    float* sA = sm + K * 128;
    int tid = threadIdx.x;

    float4* sW4 = (float4*)sW;
    const float4* Wg = (const float4*)W;
    for (int i = tid; i < K * 32; i += 256) sW4[i] = Wg[i];
    {
        int row = tid >> 2, q = tid & 3;
        int r = blockIdx.x * 64 + row;
        const int f4p = K / 16;
        float4* dst = (float4*)(sA + row * K) + q * f4p;
        if (r < M) {
            const float4* Ar = (const float4*)(A + (size_t)r * K) + q * f4p;
#pragma unroll
            for (int i = 0; i < f4p; i++) dst[i] = Ar[i];
        } else {
#pragma unroll
            for (int i = 0; i < f4p; i++) dst[i] = make_float4(0.f, 0.f, 0.f, 0.f);
        }
    }
    __syncthreads();

    int rg = tid >> 5, cg = tid & 31;
    float4 acc[8];
#pragma unroll
    for (int i = 0; i < 8; i++) acc[i] = make_float4(0.f, 0.f, 0.f, 0.f);
    const float4* sA4 = (const float4*)sA;
#pragma unroll 2
    for (int k4 = 0; k4 < K / 4; k4++) {
        float4 w0 = sW4[(4 * k4 + 0) * 32 + cg];
        float4 w1 = sW4[(4 * k4 + 1) * 32 + cg];
        float4 w2 = sW4[(4 * k4 + 2) * 32 + cg];
        float4 w3 = sW4[(4 * k4 + 3) * 32 + cg];
#pragma unroll
        for (int i = 0; i < 8; i++) {
            float4 a = sA4[(rg * 8 + i) * (K / 4) + k4];
            acc[i].x += a.x * w0.x + a.y * w1.x + a.z * w2.x + a.w * w3.x;
            acc[i].y += a.x * w0.y + a.y * w1.y + a.z * w2.y + a.w * w3.y;
            acc[i].z += a.x * w0.z + a.y * w1.z + a.z * w2.z + a.w * w3.z;
            acc[i].w += a.x * w0.w + a.y * w1.w + a.z * w2.w + a.w * w3.w;
        }
    }
    float4 bb = ((const float4*)bias)[cg];
#pragma unroll
    for (int i = 0; i < 8; i++) {
        int r = blockIdx.x * 64 + rg * 8 + i;
        if (r < M) {
            uint2 h;
            *(__half2*)&h.x = __floats2half2_rn(acc[i].x + bb.x, acc[i].y + bb.y);
            *(__half2*)&h.y = __floats2half2_rn(acc[i].z + bb.z, acc[i].w + bb.w);
            ((uint2*)(CH + (size_t)r * HH))[cg] = h;
        }
    }
}

// ---------------- weight prep: transpose + fp16 hi/lo split, half2-packed along k ---
__global__ void prepB_kernel(const float* __restrict__ W_root, const float* __restrict__ W_rel,
                             __half* __restrict__ B16) {
    int i = blockIdx.x * blockDim.x + threadIdx.x;
    if (i >= 4 * 256 * 128) return;
    int n = i & 127;
    int k = (i >> 7) & 255;
    int v = i >> 15;
    int l = v >> 1, type = v & 1;
    float val;
    if (k < 128) {
        val = W_root[((size_t)l * 128 + k) * 128 + n];
    } else {
        int rel = (type == 0) ? 1 : 0;
        val = W_rel[(((size_t)l * 2 + rel) * 128 + (k - 128)) * 128 + n];
    }
    __half hi = __float2half_rn(val);
    float lo = val - __half2float(hi);
    __half lo16 = __float2half_rn(lo);
    int k2 = k >> 1, kb = k & 1;
    size_t whi = ((size_t)(v * 2 + 0) * 16384 + (size_t)k2 * 128 + n) * 2 + kb;
    size_t wlo = ((size_t)(v * 2 + 1) * 16384 + (size_t)k2 * 128 + n) * 2 + kb;
    B16[whi] = hi;
    B16[wlo] = lo16;
}

// ---------------- mma.sync fp16 layer: out = relu([x|agg] @ (Bhi+Blo) + b) -----------
// A exact fp16 (storage format), B fp16 hi/lo 2-split. m16n8k16.
// smem (uint32 words): A stride 20 (128 rows x 16 half2 + pad4), B stride 136.
#define ASTR20  20
#define BSTR136 136
#define SM_A    0
#define SM_BH   (128 * ASTR20)                       // 2560
#define SM_BL   (128 * ASTR20 + 16 * BSTR136)        // 4736
#define SM_WORDS (128 * ASTR20 + 2 * 16 * BSTR136)   // 6912 words = 27648 B

template <bool FINAL>
__global__ void __launch_bounds__(256, 2)
layer_mma_kernel(const __half* __restrict__ X16, const __half* __restrict__ AGG16,
                 const __half* __restrict__ B16, const float* __restrict__ bias,
                 float* __restrict__ C, __half* __restrict__ CH, int layer) {
    extern __shared__ uint32_t smu[];
    int tid = threadIdx.x, wid = tid >> 5, lane = tid & 31;
    int warpM = wid & 3, warpN = wid >> 2;
    int gid = lane >> 2, tig = lane & 3;

    const int NBP_T = (NPAT + 127) / 128;   // 391
    int bid = blockIdx.x;
    int base, rowlim, v;
    if (bid < NBP_T) { base = bid * 128;                  rowlim = NPAT; v = layer * 2; }
    else             { base = NPAT + (bid - NBP_T) * 128; rowlim = NN;   v = layer * 2 + 1; }

    float acc[2][8][4];
#pragma unroll
    for (int mt = 0; mt < 2; mt++)
#pragma unroll
        for (int nt = 0; nt < 8; nt++)
#pragma unroll
            for (int r = 0; r < 4; r++) acc[mt][nt][r] = 0.f;

    int arow = tid >> 1;
    int node = base + arow;
    bool valid = node < rowlim;
    int f4base = (tid & 1) * 4;

    const uint4* bh4 = (const uint4*)(B16 + ((size_t)(v * 2 + 0) * 16384) * 2);
    const uint4* bl4 = (const uint4*)(B16 + ((size_t)(v * 2 + 1) * 16384) * 2);

    for (int chunk = 0; chunk < 8; chunk++) {
        // ---- A chunk: straight fp16 copy (32 halves/row = 16 words) ----
        const __half* src = (chunk < 4)
            ? (X16   + (size_t)node * HH + chunk * 32)
            : (AGG16 + (size_t)node * HH + (chunk - 4) * 32);
#pragma unroll
        for (int i = 0; i < 4; i++) {
            int f4 = f4base + i;
            uint2 u = valid ? ((const uint2*)src)[f4] : make_uint2(0u, 0u);
            *(uint2*)&smu[SM_A + arow * ASTR20 + f4 * 2] = u;
        }
        // ---- B chunk: 16 k2-rows x 128 n words per split; 2 uint4 per thread/split --
        {
            int gbase = chunk * 16 * 32;   // uint4 offset of chunk (16 rows x 32 uint4)
#pragma unroll
            for (int i = 0; i < 2; i++) {
                int e = tid + 256 * i;     // < 512
                int k2 = e >> 5, n4 = e & 31;
                uint4 uh = bh4[gbase + e];
                uint4 ul = bl4[gbase + e];
                *(uint4*)&smu[SM_BH + k2 * BSTR136 + n4 * 4] = uh;
                *(uint4*)&smu[SM_BL + k2 * BSTR136 + n4 * 4] = ul;
            }
        }
        __syncthreads();

#pragma unroll
        for (int step = 0; step < 2; step++) {     // 2 x k16
            int s8 = step * 8;
            uint32_t a[2][4];
#pragma unroll
            for (int mt = 0; mt < 2; mt++) {
                int r0 = warpM * 32 + mt * 16 + gid;
                a[mt][0] = smu[SM_A + r0 * ASTR20 + s8 + tig];
                a[mt][1] = smu[SM_A + (r0 + 8) * ASTR20 + s8 + tig];
                a[mt][2] = smu[SM_A + r0 * ASTR20 + s8 + 4 + tig];
                a[mt][3] = smu[SM_A + (r0 + 8) * ASTR20 + s8 + 4 + tig];
            }
#pragma unroll
            for (int nt = 0; nt < 8; nt++) {
                int n = warpN * 64 + nt * 8 + gid;
                uint32_t bh[2], bl[2];
                bh[0] = smu[SM_BH + (s8 + tig) * BSTR136 + n];
                bh[1] = smu[SM_BH + (s8 + 4 + tig) * BSTR136 + n];
                bl[0] = smu[SM_BL + (s8 + tig) * BSTR136 + n];
                bl[1] = smu[SM_BL + (s8 + 4 + tig) * BSTR136 + n];
#pragma unroll
                for (int mt = 0; mt < 2; mt++) {
                    mma_f16(acc[mt][nt], a[mt], bh);
                    mma_f16(acc[mt][nt], a[mt], bl);
                }
            }
        }
        __syncthreads();
    }

    // ---- epilogue: bias + relu ----
#pragma unroll
    for (int mt = 0; mt < 2; mt++) {
        int row = base + warpM * 32 + mt * 16 + gid;
#pragma unroll
        for (int nt = 0; nt < 8; nt++) {
            int col = warpN * 64 + nt * 8 + tig * 2;
            float2 bv = *(const float2*)&bias[col];
            if (row < rowlim) {
                float2 o;
                o.x = fmaxf(acc[mt][nt][0] + bv.x, 0.f);
                o.y = fmaxf(acc[mt][nt][1] + bv.y, 0.f);
                if (FINAL) *(float2*)&C[(size_t)row * HH + col] = o;
                else       *(__half2*)&CH[(size_t)row * HH + col] = __floats2half2_rn(o.x, o.y);
            }
            if (row + 8 < rowlim) {
                float2 o;
                o.x = fmaxf(acc[mt][nt][2] + bv.x, 0.f);
                o.y = fmaxf(acc[mt][nt][3] + bv.y, 0.f);
                if (FINAL) *(float2*)&C[(size_t)(row + 8) * HH + col] = o;
                else       *(__half2*)&CH[(size_t)(row + 8) * HH + col] = __floats2half2_rn(o.x, o.y);
            }
        }
    }
}

// ---------------- launch ----------------
extern "C" void kernel_launch(void* const* d_in, const int* in_sizes, int n_in,
                              void* d_out, int out_size) {
    const float* x_patient = (const float*)d_in[0];
    const float* x_concept = (const float*)d_in[1];
    const float* W_p    = (const float*)d_in[2];
    const float* b_p    = (const float*)d_in[3];
    const float* W_c    = (const float*)d_in[4];
    const float* b_c    = (const float*)d_in[5];
    const float* W_root = (const float*)d_in[6];
    const float* b_root = (const float*)d_in[7];
    const float* W_rel  = (const float*)d_in[8];
    const int* src_pc = (const int*)d_in[9];
    const int* dst_pc = (const int*)d_in[10];
    const int* src_cp = (const int*)d_in[11];
    const int* dst_cp = (const int*)d_in[12];
    float* out = (float*)d_out;

    float *rcnt;
    __half *h0, *h1, *agg16, *Bg16;
    int *deg, *off, *cur, *csr;
    cudaGetSymbolAddress((void**)&h0,    g_h0);
    cudaGetSymbolAddress((void**)&h1,    g_h1);
    cudaGetSymbolAddress((void**)&agg16, g_agg16);
    cudaGetSymbolAddress((void**)&rcnt,  g_rcnt);
    cudaGetSymbolAddress((void**)&deg,   g_deg);
    cudaGetSymbolAddress((void**)&off,   g_off);
    cudaGetSymbolAddress((void**)&cur,   g_cur);
    cudaGetSymbolAddress((void**)&csr,   g_csr);
    cudaGetSymbolAddress((void**)&Bg16,  g_B16);

    const int PROJ64_SMEM  = (64  * 128 + 64 * 64 ) * 4;
    const int PROJ128_SMEM = (128 * 128 + 64 * 128) * 4;
    const int LAYER_SMEM   = SM_WORDS * 4;               // 27648 B
    cudaFuncSetAttribute(proj_kernel<64>,  cudaFuncAttributeMaxDynamicSharedMemorySize, PROJ64_SMEM);
    cudaFuncSetAttribute(proj_kernel<128>, cudaFuncAttributeMaxDynamicSharedMemorySize, PROJ128_SMEM);
    cudaFuncSetAttribute(layer_mma_kernel<false>, cudaFuncAttributeMaxDynamicSharedMemorySize, LAYER_SMEM);
    cudaFuncSetAttribute(layer_mma_kernel<true>,  cudaFuncAttributeMaxDynamicSharedMemorySize, LAYER_SMEM);

    // ---- CSR build ----
    cudaMemsetAsync(deg, 0, NN * sizeof(int));
    cudaMemsetAsync(cur, 0, NN * sizeof(int));
    deg_kernel<<<(2 * EE + 255) / 256, 256>>>(dst_pc, dst_cp, deg);
    scan_kernel<<<1, 1024>>>(deg, off);
    rcnt_kernel<<<(NN + 255) / 256, 256>>>(deg, rcnt);
    fill_kernel<<<(2 * EE + 255) / 256, 256>>>(src_pc, dst_pc, src_cp, dst_cp, off, cur, csr);

    // ---- weight prep ----
    prepB_kernel<<<(4 * 256 * 128 + 255) / 256, 256>>>(W_root, W_rel, Bg16);

    // ---- projections (fp32 FFMA compute, fp16 store) ----
    proj_kernel<64><<<(NPAT + 63) / 64, 256, PROJ64_SMEM>>>(x_patient, W_p, b_p, h0, NPAT);
    proj_kernel<128><<<(NCON + 63) / 64, 256, PROJ128_SMEM>>>(x_concept, W_c, b_c,
                                                              h0 + (size_t)NPAT * HH, NCON);

    const int NB_TC = (NPAT + 127) / 128 + (NCON + 127) / 128;  // 548
    const int GATHER_BLOCKS = (NN + 7) / 8;

    // ---- layer 0 (fp16 out) ----
    gather_kernel<<<GATHER_BLOCKS, 256>>>(h0, off, csr, rcnt, agg16);
    layer_mma_kernel<false><<<NB_TC, 256, LAYER_SMEM>>>(h0, agg16, Bg16, b_root,
                                                        (float*)nullptr, h1, 0);
    // ---- layer 1 (fp32 out) ----
    gather_kernel<<<GATHER_BLOCKS, 256>>>(h1, off, csr, rcnt, agg16);
    layer_mma_kernel<true><<<NB_TC, 256, LAYER_SMEM>>>(h1, agg16, Bg16, b_root + HH,
                                                       out, (__half*)nullptr, 1);
}

// round 14
// speedup vs baseline: 1.8622x; 1.1377x over previous
#include <cuda_runtime.h>
#include <cuda_fp16.h>
#include <cstdint>

#define NPAT 50000
#define NCON 20000
#define NN   70000
#define EE   800000
#define HH   128
#define LL   2

// ---------------- scratch (static device globals; no allocs allowed) ----------------
__device__ __half g_h0   [(size_t)NN * HH];   // proj output / layer-0 input
__device__ __half g_h1   [(size_t)NN * HH];   // layer-0 output / layer-1 input
__device__ __half g_agg16[(size_t)NN * HH];   // neighbor mean (fp32 accum, fp16 store)
__device__ int    g_deg [NN];
__device__ float  g_rcnt[NN];
__device__ int    g_off [NN + 1];
__device__ int    g_cur [NN];
__device__ int    g_csr [2 * EE];
// fp16 hi/lo split weights, half2-packed along k.
// Layer variant v occupies halves [v*65536, v*65536+32768) = hi, [+32768, +65536) = lo.
__device__ __half g_B16[(size_t)8 * 128 * 128 * 2];   // 4 variants x (hi+lo) x 32768
__device__ __half g_Bp16[2 * 64 * 128];               // W_p hi/lo (K=64)
__device__ __half g_Bc16[2 * 128 * 128];              // W_c hi/lo (K=128)

// ---------------- helpers ----------------
__device__ __forceinline__ void mma_f16(float* c, const uint32_t* a, const uint32_t* b) {
    asm volatile(
        "mma.sync.aligned.m16n8k16.row.col.f32.f16.f16.f32 "
        "{%0,%1,%2,%3}, {%4,%5,%6,%7}, {%8,%9}, {%0,%1,%2,%3};"
        : "+f"(c[0]), "+f"(c[1]), "+f"(c[2]), "+f"(c[3])
        : "r"(a[0]), "r"(a[1]), "r"(a[2]), "r"(a[3]),
          "r"(b[0]), "r"(b[1]));
}

// ---------------- degree histogram ----------------
__global__ void deg_kernel(const int* __restrict__ dst_pc, const int* __restrict__ dst_cp,
                           int* __restrict__ deg) {
    int i = blockIdx.x * blockDim.x + threadIdx.x;
    if (i < EE)               atomicAdd(&deg[NPAT + dst_pc[i]], 1);
    else if (i < 2 * EE)      atomicAdd(&deg[dst_cp[i - EE]], 1);
}

__global__ void rcnt_kernel(const int* __restrict__ deg, float* __restrict__ rcnt) {
    int i = blockIdx.x * blockDim.x + threadIdx.x;
    if (i < NN) rcnt[i] = 1.0f / (float)max(deg[i], 1);
}

// ---------------- single-block exclusive scan ----------------
__global__ void scan_kernel(const int* __restrict__ deg, int* __restrict__ off) {
    __shared__ int ssum[1024];
    int tid = threadIdx.x;
    const int PER = (NN + 1023) / 1024;
    int base = tid * PER;
    int s = 0;
    for (int i = 0; i < PER; i++) { int idx = base + i; if (idx < NN) s += deg[idx]; }
    ssum[tid] = s;
    __syncthreads();
    for (int ofs = 1; ofs < 1024; ofs <<= 1) {
        int v = (tid >= ofs) ? ssum[tid - ofs] : 0;
        __syncthreads();
        ssum[tid] += v;
        __syncthreads();
    }
    int run = (tid == 0) ? 0 : ssum[tid - 1];
    for (int i = 0; i < PER; i++) {
        int idx = base + i;
        if (idx < NN) { off[idx] = run; run += deg[idx]; }
    }
    if (tid == 0) off[NN] = ssum[1023];
}

// ---------------- CSR fill ----------------
__global__ void fill_kernel(const int* __restrict__ src_pc, const int* __restrict__ dst_pc,
                            const int* __restrict__ src_cp, const int* __restrict__ dst_cp,
                            const int* __restrict__ off, int* __restrict__ cur,
                            int* __restrict__ csr) {
    int i = blockIdx.x * blockDim.x + threadIdx.x;
    int s, d;
    if (i < EE)          { s = src_pc[i];             d = NPAT + dst_pc[i]; }
    else if (i < 2 * EE) { s = NPAT + src_cp[i - EE]; d = dst_cp[i - EE]; }
    else return;
    int pos = off[d] + atomicAdd(&cur[d], 1);
    csr[pos] = s;
}

// ---------------- fp16 gather-aggregate (fp32 accumulate, fp16 store) ---------------
__global__ void gather_kernel(const __half* __restrict__ X16,
                              const int* __restrict__ off, const int* __restrict__ csr,
                              const float* __restrict__ rcnt, __half* __restrict__ AGG16) {
    int warp = (int)((blockIdx.x * (long long)blockDim.x + threadIdx.x) >> 5);
    if (warp >= NN) return;
    int lane = threadIdx.x & 31;
    int beg = off[warp], end = off[warp + 1];
    float4 acc = make_float4(0.f, 0.f, 0.f, 0.f);
    int e = beg;
    for (; e + 32 <= end; e += 32) {
        int idx = csr[e + lane];
#pragma unroll
        for (int j = 0; j < 32; j++) {
            int s = __shfl_sync(0xffffffffu, idx, j);
            uint2 u = ((const uint2*)(X16 + (size_t)s * HH))[lane];
            float2 f0 = __half22float2(*(__half2*)&u.x);
            float2 f1 = __half22float2(*(__half2*)&u.y);
            acc.x += f0.x; acc.y += f0.y; acc.z += f1.x; acc.w += f1.y;
        }
    }
    int rem = end - e;
    if (rem > 0) {
        int idx = (lane < rem) ? csr[e + lane] : 0;
        for (int j = 0; j < rem; j++) {
            int s = __shfl_sync(0xffffffffu, idx, j);
            uint2 u = ((const uint2*)(X16 + (size_t)s * HH))[lane];
            float2 f0 = __half22float2(*(__half2*)&u.x);
            float2 f1 = __half22float2(*(__half2*)&u.y);
            acc.x += f0.x; acc.y += f0.y; acc.z += f1.x; acc.w += f1.y;
        }
    }
    float rc = rcnt[warp];
    uint2 o;
    *(__half2*)&o.x = __floats2half2_rn(acc.x * rc, acc.y * rc);
    *(__half2*)&o.y = __floats2half2_rn(acc.z * rc, acc.w * rc);
    ((uint2*)(AGG16 + (size_t)warp * HH))[lane] = o;
}

// ---------------- weight prep: fp16 hi/lo split, half2-packed along k ---------------
// ranges: [0,131072) layer variants; [131072,139264) W_p; [139264,155648) W_c
__global__ void prepB_kernel(const float* __restrict__ W_root, const float* __restrict__ W_rel,
                             const float* __restrict__ W_p, const float* __restrict__ W_c,
                             __half* __restrict__ B16, __half* __restrict__ Bp16,
                             __half* __restrict__ Bc16) {
    int i = blockIdx.x * blockDim.x + threadIdx.x;
    float val; int k, n;
    __half* dst; size_t stride_split;
    if (i < 131072) {
        int v = i >> 15, rem = i & 32767;
        k = rem >> 7; n = rem & 127;
        int l = v >> 1, type = v & 1;
        if (k < 128) val = W_root[((size_t)l * 128 + k) * 128 + n];
        else {
            int rel = (type == 0) ? 1 : 0;
            val = W_rel[(((size_t)l * 2 + rel) * 128 + (k - 128)) * 128 + n];
        }
        dst = B16 + (size_t)v * 65536;    // FIX: 65536 halves per variant (hi+lo)
        stride_split = 32768;             // FIX: 32768 halves per split (K=256)
    } else if (i < 139264) {
        int rem = i - 131072;
        k = rem >> 7; n = rem & 127;
        val = W_p[k * 128 + n];
        dst = Bp16;
        stride_split = 8192;              // K=64: 8192 halves per split
    } else if (i < 155648) {
        int rem = i - 139264;
        k = rem >> 7; n = rem & 127;
        val = W_c[k * 128 + n];
        dst = Bc16;
        stride_split = 16384;             // K=128: 16384 halves per split
    } else return;
    __half hi = __float2half_rn(val);
    float lo = val - __half2float(hi);
    __half lo16 = __float2half_rn(lo);
    int k2 = k >> 1, kb = k & 1;
    size_t idx = ((size_t)k2 * 128 + n) * 2 + kb;
    dst[idx] = hi;
    dst[stride_split + idx] = lo16;
}

// ---------------- shared mma-tile smem layout ---------------------------------------
#define ASTR20  20
#define BSTR136 136
#define SM_A    0
#define SM_BH   (128 * ASTR20)                       // 2560
#define SM_BL   (128 * ASTR20 + 16 * BSTR136)        // 4736
#define SM_WORDS (128 * ASTR20 + 2 * 16 * BSTR136)   // 6912 words = 27648 B

// ---------------- projection MMA: CH[M,128] = fp16(A[M,K] @ W + b) -------------------
template <int KCH>
__global__ void __launch_bounds__(256, 2)
proj_mma_kernel(const float* __restrict__ A, const __half* __restrict__ Bsp,
                const float* __restrict__ bias, __half* __restrict__ CH, int M) {
    extern __shared__ uint32_t smu[];
    int tid = threadIdx.x, wid = tid >> 5, lane = tid & 31;
    int warpM = wid & 3, warpN = wid >> 2;
    int gid = lane >> 2, tig = lane & 3;
    const int K = KCH * 32;
    const int SPLIT_HALVES = KCH * 32 * 128;   // halves per split

    float acc[2][8][4];
#pragma unroll
    for (int mt = 0; mt < 2; mt++)
#pragma unroll
        for (int nt = 0; nt < 8; nt++)
#pragma unroll
            for (int r = 0; r < 4; r++) acc[mt][nt][r] = 0.f;

    int arow = tid >> 1;
    int lr = blockIdx.x * 128 + arow;
    bool valid = lr < M;
    int f4base = (tid & 1) * 4;

    const uint4* bh4 = (const uint4*)(Bsp);
    const uint4* bl4 = (const uint4*)(Bsp + SPLIT_HALVES);

#pragma unroll
    for (int chunk = 0; chunk < KCH; chunk++) {
        // ---- A chunk: fp32 load, fp16 convert ----
        const float4* src4 = (const float4*)(A + (size_t)lr * K + chunk * 32);
#pragma unroll
        for (int i = 0; i < 4; i++) {
            int f4 = f4base + i;
            float4 a = valid ? src4[f4] : make_float4(0.f, 0.f, 0.f, 0.f);
            uint2 u;
            *(__half2*)&u.x = __floats2half2_rn(a.x, a.y);
            *(__half2*)&u.y = __floats2half2_rn(a.z, a.w);
            *(uint2*)&smu[SM_A + arow * ASTR20 + f4 * 2] = u;
        }
        // ---- B chunk ----
        {
            int gbase = chunk * 16 * 32;
#pragma unroll
            for (int i = 0; i < 2; i++) {
                int e = tid + 256 * i;
                int k2 = e >> 5, n4 = e & 31;
                uint4 uh = bh4[gbase + e];
                uint4 ul = bl4[gbase + e];
                *(uint4*)&smu[SM_BH + k2 * BSTR136 + n4 * 4] = uh;
                *(uint4*)&smu[SM_BL + k2 * BSTR136 + n4 * 4] = ul;
            }
        }
        __syncthreads();

#pragma unroll
        for (int step = 0; step < 2; step++) {
            int s8 = step * 8;
            uint32_t a[2][4];
#pragma unroll
            for (int mt = 0; mt < 2; mt++) {
                int r0 = warpM * 32 + mt * 16 + gid;
                a[mt][0] = smu[SM_A + r0 * ASTR20 + s8 + tig];
                a[mt][1] = smu[SM_A + (r0 + 8) * ASTR20 + s8 + tig];
                a[mt][2] = smu[SM_A + r0 * ASTR20 + s8 + 4 + tig];
                a[mt][3] = smu[SM_A + (r0 + 8) * ASTR20 + s8 + 4 + tig];
            }
#pragma unroll
            for (int nt = 0; nt < 8; nt++) {
                int n = warpN * 64 + nt * 8 + gid;
                uint32_t bh[2], bl[2];
                bh[0] = smu[SM_BH + (s8 + tig) * BSTR136 + n];
                bh[1] = smu[SM_BH + (s8 + 4 + tig) * BSTR136 + n];
                bl[0] = smu[SM_BL + (s8 + tig) * BSTR136 + n];
                bl[1] = smu[SM_BL + (s8 + 4 + tig) * BSTR136 + n];
#pragma unroll
                for (int mt = 0; mt < 2; mt++) {
                    mma_f16(acc[mt][nt], a[mt], bh);
                    mma_f16(acc[mt][nt], a[mt], bl);
                }
            }
        }
        __syncthreads();
    }

#pragma unroll
    for (int mt = 0; mt < 2; mt++) {
        int row = blockIdx.x * 128 + warpM * 32 + mt * 16 + gid;
#pragma unroll
        for (int nt = 0; nt < 8; nt++) {
            int col = warpN * 64 + nt * 8 + tig * 2;
            float2 bv = *(const float2*)&bias[col];
            if (row < M)
                *(__half2*)&CH[(size_t)row * HH + col] =
                    __floats2half2_rn(acc[mt][nt][0] + bv.x, acc[mt][nt][1] + bv.y);
            if (row + 8 < M)
                *(__half2*)&CH[(size_t)(row + 8) * HH + col] =
                    __floats2half2_rn(acc[mt][nt][2] + bv.x, acc[mt][nt][3] + bv.y);
        }
    }
}

// ---------------- mma.sync fp16 layer: out = relu([x|agg] @ (Bhi+Blo) + b) -----------
template <bool FINAL>
__global__ void __launch_bounds__(256, 2)
layer_mma_kernel(const __half* __restrict__ X16, const __half* __restrict__ AGG16,
                 const __half* __restrict__ B16, const float* __restrict__ bias,
                 float* __restrict__ C, __half* __restrict__ CH, int layer) {
    extern __shared__ uint32_t smu[];
    int tid = threadIdx.x, wid = tid >> 5, lane = tid & 31;
    int warpM = wid & 3, warpN = wid >> 2;
    int gid = lane >> 2, tig = lane & 3;

    const int NBP_T = (NPAT + 127) / 128;   // 391
    int bid = blockIdx.x;
    int base, rowlim, v;
    if (bid < NBP_T) { base = bid * 128;                  rowlim = NPAT; v = layer * 2; }
    else             { base = NPAT + (bid - NBP_T) * 128; rowlim = NN;   v = layer * 2 + 1; }

    float acc[2][8][4];
#pragma unroll
    for (int mt = 0; mt < 2; mt++)
#pragma unroll
        for (int nt = 0; nt < 8; nt++)
#pragma unroll
            for (int r = 0; r < 4; r++) acc[mt][nt][r] = 0.f;

    int arow = tid >> 1;
    int node = base + arow;
    bool valid = node < rowlim;
    int f4base = (tid & 1) * 4;

    const uint4* bh4 = (const uint4*)(B16 + (size_t)v * 65536);            // FIX
    const uint4* bl4 = (const uint4*)(B16 + (size_t)v * 65536 + 32768);    // FIX

    for (int chunk = 0; chunk < 8; chunk++) {
        const __half* src = (chunk < 4)
            ? (X16   + (size_t)node * HH + chunk * 32)
            : (AGG16 + (size_t)node * HH + (chunk - 4) * 32);
#pragma unroll
        for (int i = 0; i < 4; i++) {
            int f4 = f4base + i;
            uint2 u = valid ? ((const uint2*)src)[f4] : make_uint2(0u, 0u);
            *(uint2*)&smu[SM_A + arow * ASTR20 + f4 * 2] = u;
        }
        {
            int gbase = chunk * 16 * 32;
#pragma unroll
            for (int i = 0; i < 2; i++) {
                int e = tid + 256 * i;
                int k2 = e >> 5, n4 = e & 31;
                uint4 uh = bh4[gbase + e];
                uint4 ul = bl4[gbase + e];
                *(uint4*)&smu[SM_BH + k2 * BSTR136 + n4 * 4] = uh;
                *(uint4*)&smu[SM_BL + k2 * BSTR136 + n4 * 4] = ul;
            }
        }
        __syncthreads();

#pragma unroll
        for (int step = 0; step < 2; step++) {
            int s8 = step * 8;
            uint32_t a[2][4];
#pragma unroll
            for (int mt = 0; mt < 2; mt++) {
                int r0 = warpM * 32 + mt * 16 + gid;
                a[mt][0] = smu[SM_A + r0 * ASTR20 + s8 + tig];
                a[mt][1] = smu[SM_A + (r0 + 8) * ASTR20 + s8 + tig];
                a[mt][2] = smu[SM_A + r0 * ASTR20 + s8 + 4 + tig];
                a[mt][3] = smu[SM_A + (r0 + 8) * ASTR20 + s8 + 4 + tig];
            }
#pragma unroll
            for (int nt = 0; nt < 8; nt++) {
                int n = warpN * 64 + nt * 8 + gid;
                uint32_t bh[2], bl[2];
                bh[0] = smu[SM_BH + (s8 + tig) * BSTR136 + n];
                bh[1] = smu[SM_BH + (s8 + 4 + tig) * BSTR136 + n];
                bl[0] = smu[SM_BL + (s8 + tig) * BSTR136 + n];
                bl[1] = smu[SM_BL + (s8 + 4 + tig) * BSTR136 + n];
#pragma unroll
                for (int mt = 0; mt < 2; mt++) {
                    mma_f16(acc[mt][nt], a[mt], bh);
                    mma_f16(acc[mt][nt], a[mt], bl);
                }
            }
        }
        __syncthreads();
    }

#pragma unroll
    for (int mt = 0; mt < 2; mt++) {
        int row = base + warpM * 32 + mt * 16 + gid;
#pragma unroll
        for (int nt = 0; nt < 8; nt++) {
            int col = warpN * 64 + nt * 8 + tig * 2;
            float2 bv = *(const float2*)&bias[col];
            if (row < rowlim) {
                float2 o;
                o.x = fmaxf(acc[mt][nt][0] + bv.x, 0.f);
                o.y = fmaxf(acc[mt][nt][1] + bv.y, 0.f);
                if (FINAL) *(float2*)&C[(size_t)row * HH + col] = o;
                else       *(__half2*)&CH[(size_t)row * HH + col] = __floats2half2_rn(o.x, o.y);
            }
            if (row + 8 < rowlim) {
                float2 o;
                o.x = fmaxf(acc[mt][nt][2] + bv.x, 0.f);
                o.y = fmaxf(acc[mt][nt][3] + bv.y, 0.f);
                if (FINAL) *(float2*)&C[(size_t)(row + 8) * HH + col] = o;
                else       *(__half2*)&CH[(size_t)(row + 8) * HH + col] = __floats2half2_rn(o.x, o.y);
            }
        }
    }
}

// ---------------- launch ----------------
extern "C" void kernel_launch(void* const* d_in, const int* in_sizes, int n_in,
                              void* d_out, int out_size) {
    const float* x_patient = (const float*)d_in[0];
    const float* x_concept = (const float*)d_in[1];
    const float* W_p    = (const float*)d_in[2];
    const float* b_p    = (const float*)d_in[3];
    const float* W_c    = (const float*)d_in[4];
    const float* b_c    = (const float*)d_in[5];
    const float* W_root = (const float*)d_in[6];
    const float* b_root = (const float*)d_in[7];
    const float* W_rel  = (const float*)d_in[8];
    const int* src_pc = (const int*)d_in[9];
    const int* dst_pc = (const int*)d_in[10];
    const int* src_cp = (const int*)d_in[11];
    const int* dst_cp = (const int*)d_in[12];
    float* out = (float*)d_out;

    float *rcnt;
    __half *h0, *h1, *agg16, *Bg16, *Bp16, *Bc16;
    int *deg, *off, *cur, *csr;
    cudaGetSymbolAddress((void**)&h0,    g_h0);
    cudaGetSymbolAddress((void**)&h1,    g_h1);
    cudaGetSymbolAddress((void**)&agg16, g_agg16);
    cudaGetSymbolAddress((void**)&rcnt,  g_rcnt);
    cudaGetSymbolAddress((void**)&deg,   g_deg);
    cudaGetSymbolAddress((void**)&off,   g_off);
    cudaGetSymbolAddress((void**)&cur,   g_cur);
    cudaGetSymbolAddress((void**)&csr,   g_csr);
    cudaGetSymbolAddress((void**)&Bg16,  g_B16);
    cudaGetSymbolAddress((void**)&Bp16,  g_Bp16);
    cudaGetSymbolAddress((void**)&Bc16,  g_Bc16);

    const int LAYER_SMEM = SM_WORDS * 4;                 // 27648 B
    cudaFuncSetAttribute(proj_mma_kernel<2>, cudaFuncAttributeMaxDynamicSharedMemorySize, LAYER_SMEM);
    cudaFuncSetAttribute(proj_mma_kernel<4>, cudaFuncAttributeMaxDynamicSharedMemorySize, LAYER_SMEM);
    cudaFuncSetAttribute(layer_mma_kernel<false>, cudaFuncAttributeMaxDynamicSharedMemorySize, LAYER_SMEM);
    cudaFuncSetAttribute(layer_mma_kernel<true>,  cudaFuncAttributeMaxDynamicSharedMemorySize, LAYER_SMEM);

    // ---- CSR build ----
    cudaMemsetAsync(deg, 0, NN * sizeof(int));
    cudaMemsetAsync(cur, 0, NN * sizeof(int));
    deg_kernel<<<(2 * EE + 255) / 256, 256>>>(dst_pc, dst_cp, deg);
    scan_kernel<<<1, 1024>>>(deg, off);
    rcnt_kernel<<<(NN + 255) / 256, 256>>>(deg, rcnt);
    fill_kernel<<<(2 * EE + 255) / 256, 256>>>(src_pc, dst_pc, src_cp, dst_cp, off, cur, csr);

    // ---- weight prep (layers + projections) ----
    prepB_kernel<<<(155648 + 255) / 256, 256>>>(W_root, W_rel, W_p, W_c, Bg16, Bp16, Bc16);

    // ---- projections (fp16 MMA) ----
    proj_mma_kernel<2><<<(NPAT + 127) / 128, 256, LAYER_SMEM>>>(x_patient, Bp16, b_p, h0, NPAT);
    proj_mma_kernel<4><<<(NCON + 127) / 128, 256, LAYER_SMEM>>>(x_concept, Bc16, b_c,
                                                                h0 + (size_t)NPAT * HH, NCON);

    const int NB_TC = (NPAT + 127) / 128 + (NCON + 127) / 128;  // 548
    const int GATHER_BLOCKS = (NN + 7) / 8;

    // ---- layer 0 (fp16 out) ----
    gather_kernel<<<GATHER_BLOCKS, 256>>>(h0, off, csr, rcnt, agg16);
    layer_mma_kernel<false><<<NB_TC, 256, LAYER_SMEM>>>(h0, agg16, Bg16, b_root,
                                                        (float*)nullptr, h1, 0);
    // ---- layer 1 (fp32 out) ----
    gather_kernel<<<GATHER_BLOCKS, 256>>>(h1, off, csr, rcnt, agg16);
    layer_mma_kernel<true><<<NB_TC, 256, LAYER_SMEM>>>(h1, agg16, Bg16, b_root + HH,
                                                       out, (__half*)nullptr, 1);
}